// round 4
// baseline (speedup 1.0000x reference)
#include <cuda_runtime.h>

#define NN 100000
#define NE 3200000
#define NG 1024
#define D  128
#define BN_EPS 1e-5f

typedef unsigned long long ull;

// ---------------- scratch (static device globals; no runtime alloc) ----------
__device__ float g_agg[(size_t)NN * D];   // hin = h + sum_neighbors
__device__ float g_h1 [(size_t)NN * D];   // pre-BN hidden
__device__ float g_hA [(size_t)NN * D];   // layer output ping
__device__ float g_hB [(size_t)NN * D];   // layer output pong
__device__ int   g_rowptr[NN + 1];
__device__ int   g_cnt[NN];               // histogram, then fill cursor
__device__ int   g_csrc[NE];              // CSR: src node ids grouped by dst
__device__ float g_stats[2 * D];          // col sum, col sumsq
__device__ float g_scale[D];
__device__ float g_shift[D];
__device__ float g_pooled[(size_t)NG * 4 * D];
__device__ int   g_gstart[NG + 1];
__device__ float g_c1[NG * D];
__device__ float g_c2[NG * (D / 2)];

// ---------------- packed f32x2 helpers ---------------------------------------
__device__ __forceinline__ ull pack2(float x, float y) {
    ull r; asm("mov.b64 %0, {%1, %2};" : "=l"(r) : "f"(x), "f"(y)); return r;
}
__device__ __forceinline__ ull fma2(ull a, ull b, ull c) {
    ull d; asm("fma.rn.f32x2 %0, %1, %2, %3;" : "=l"(d) : "l"(a), "l"(b), "l"(c)); return d;
}
__device__ __forceinline__ void unpack2(ull v, float& lo, float& hi) {
    asm("mov.b64 {%0, %1}, %2;" : "=f"(lo), "=f"(hi) : "l"(v));
}

// ---------------- init: zero cnt, zero stats, graph boundaries ----------------
__global__ void k_init(const int* __restrict__ batch) {
    int i = blockIdx.x * blockDim.x + threadIdx.x;
    if (i < NN) g_cnt[i] = 0;
    if (i < 2 * D) g_stats[i] = 0.f;
    if (i <= NG) {
        if (i == NG) { g_gstart[NG] = NN; }
        else {
            int lo = 0, hi = NN;
            while (lo < hi) { int mid = (lo + hi) >> 1; if (batch[mid] < i) lo = mid + 1; else hi = mid; }
            g_gstart[i] = lo;
        }
    }
}

__global__ void k_hist(const int* __restrict__ dst) {
    for (int e = blockIdx.x * blockDim.x + threadIdx.x; e < NE; e += gridDim.x * blockDim.x)
        atomicAdd(&g_cnt[dst[e]], 1);
}

__global__ void k_scan() {   // one block, 1024 threads; also resets g_cnt to 0
    __shared__ int totals[1024];
    int t = threadIdx.x;
    const int CH = (NN + 1023) / 1024;   // 98
    int start = t * CH;
    int end   = start + CH; if (end > NN) end = NN;
    int s = 0;
    for (int i = start; i < end; i++) s += g_cnt[i];
    totals[t] = s;
    __syncthreads();
    if (t == 0) {
        int run = 0;
        for (int i = 0; i < 1024; i++) { int v = totals[i]; totals[i] = run; run += v; }
        g_rowptr[NN] = run;   // == NE
    }
    __syncthreads();
    int run = totals[t];
    for (int i = start; i < end; i++) {
        g_rowptr[i] = run; run += g_cnt[i];
        g_cnt[i] = 0;                       // reset cursor for scatter
    }
}

__global__ void k_scatter(const int* __restrict__ src, const int* __restrict__ dst) {
    for (int e = blockIdx.x * blockDim.x + threadIdx.x; e < NE; e += gridDim.x * blockDim.x) {
        int d = dst[e];
        int pos = g_rowptr[d] + atomicAdd(&g_cnt[d], 1);
        g_csrc[pos] = src[e];
    }
}

// ---------------- aggregation: hin[i] = h[i] + sum_{e in CSR(i)} h[src(e)] ----
__global__ void k_agg(const float* __restrict__ h) {
    int i = blockIdx.x;
    int t = threadIdx.x;
    int e0 = g_rowptr[i], e1 = g_rowptr[i + 1];
    float acc = h[(size_t)i * D + t];
    int e = e0;
    for (; e + 4 <= e1; e += 4) {
        int s0 = g_csrc[e], s1 = g_csrc[e + 1], s2 = g_csrc[e + 2], s3 = g_csrc[e + 3];
        float v0 = h[(size_t)s0 * D + t];
        float v1 = h[(size_t)s1 * D + t];
        float v2 = h[(size_t)s2 * D + t];
        float v3 = h[(size_t)s3 * D + t];
        acc += (v0 + v1) + (v2 + v3);
    }
    for (; e < e1; e++) acc += h[(size_t)g_csrc[e] * D + t];
    g_agg[(size_t)i * D + t] = acc;
}

// ---------------- GEMM: C[M,128] = op(A)[M,128] @ W[128,128] + b --------------
// 128x128 block tile, 256 threads, 8x8 per-thread, f32x2 packed accumulators.
// MODE 0: plain A, no output relu; fused BN statistics (column sum/sumsq -> g_stats)
// MODE 1: A' = relu(A*scale + shift) per column (fused BN+ReLU), output relu
template <int MODE>
__global__ void __launch_bounds__(256, 2) k_gemm(const float* __restrict__ A,
                                                 const float* __restrict__ W,
                                                 const float* __restrict__ bias,
                                                 float* __restrict__ C) {
    __shared__ float As[128][40];    // 128 rows x 32 K (pad 40 keeps 16B align, spreads banks)
    __shared__ float Ws[32][128];    // 32 K x 128 cols
    const int tid  = threadIdx.x;
    const int lane = tid & 31;
    const int warp = tid >> 5;
    const int rg = (warp << 1) | (lane >> 4);   // 0..15 row group (8 rows)
    const int cg = lane & 15;                   // 0..15 col group (8 cols)
    const int m0 = blockIdx.x * 128;

    ull acc[8][4];
#pragma unroll
    for (int r = 0; r < 8; r++)
#pragma unroll
        for (int c = 0; c < 4; c++) acc[r][c] = pack2(0.f, 0.f);

    for (int k0 = 0; k0 < D; k0 += 32) {
        // A tile: 128x32 = 1024 float4, 4 per thread
#pragma unroll
        for (int j = 0; j < 4; j++) {
            int f = j * 256 + tid;
            int r = f >> 3, kq = f & 7;
            int row = m0 + r;
            float4 v = make_float4(0.f, 0.f, 0.f, 0.f);
            if (row < NN) v = *(const float4*)(A + (size_t)row * D + k0 + kq * 4);
            if (MODE == 1) {
                float4 sc = *(const float4*)(g_scale + k0 + kq * 4);
                float4 sh = *(const float4*)(g_shift + k0 + kq * 4);
                v.x = fmaxf(fmaf(v.x, sc.x, sh.x), 0.f);
                v.y = fmaxf(fmaf(v.y, sc.y, sh.y), 0.f);
                v.z = fmaxf(fmaf(v.z, sc.z, sh.z), 0.f);
                v.w = fmaxf(fmaf(v.w, sc.w, sh.w), 0.f);
            }
            *(float4*)&As[r][kq * 4] = v;
        }
        // W tile: 32x128 = 1024 float4, 4 per thread
#pragma unroll
        for (int j = 0; j < 4; j++) {
            int f = j * 256 + tid;
            int k = f >> 5, q = f & 31;
            *(float4*)&Ws[k][q * 4] = *(const float4*)(W + (size_t)(k0 + k) * D + q * 4);
        }
        __syncthreads();
#pragma unroll
        for (int k = 0; k < 32; k++) {
            // 8 output cols as 4 packed pairs straight from LDS.128 (no pack cost)
            ulonglong2 w01 = *(const ulonglong2*)&Ws[k][cg * 8];
            ulonglong2 w23 = *(const ulonglong2*)&Ws[k][cg * 8 + 4];
#pragma unroll
            for (int r = 0; r < 8; r++) {
                float a = As[rg * 8 + r][k];
                ull aa = pack2(a, a);
                acc[r][0] = fma2(aa, w01.x, acc[r][0]);
                acc[r][1] = fma2(aa, w01.y, acc[r][1]);
                acc[r][2] = fma2(aa, w23.x, acc[r][2]);
                acc[r][3] = fma2(aa, w23.y, acc[r][3]);
            }
        }
        __syncthreads();
    }

    float4 bv0 = *(const float4*)(bias + cg * 8);
    float4 bv1 = *(const float4*)(bias + cg * 8 + 4);
    float ssum[8], ssq[8];
    if (MODE == 0) {
#pragma unroll
        for (int c = 0; c < 8; c++) { ssum[c] = 0.f; ssq[c] = 0.f; }
    }

#pragma unroll
    for (int r = 0; r < 8; r++) {
        int row = m0 + rg * 8 + r;
        if (row < NN) {
            float o[8];
            unpack2(acc[r][0], o[0], o[1]);
            unpack2(acc[r][1], o[2], o[3]);
            unpack2(acc[r][2], o[4], o[5]);
            unpack2(acc[r][3], o[6], o[7]);
            o[0] += bv0.x; o[1] += bv0.y; o[2] += bv0.z; o[3] += bv0.w;
            o[4] += bv1.x; o[5] += bv1.y; o[6] += bv1.z; o[7] += bv1.w;
            if (MODE == 1) {
#pragma unroll
                for (int c = 0; c < 8; c++) o[c] = fmaxf(o[c], 0.f);
            } else {
#pragma unroll
                for (int c = 0; c < 8; c++) { ssum[c] += o[c]; ssq[c] = fmaf(o[c], o[c], ssq[c]); }
            }
            float4 v0 = make_float4(o[0], o[1], o[2], o[3]);
            float4 v1 = make_float4(o[4], o[5], o[6], o[7]);
            *(float4*)(C + (size_t)row * D + cg * 8)     = v0;
            *(float4*)(C + (size_t)row * D + cg * 8 + 4) = v1;
        }
    }

    if (MODE == 0) {
        // fused BN statistics: 16 no-return global reductions per thread
#pragma unroll
        for (int c = 0; c < 8; c++) {
            atomicAdd(&g_stats[cg * 8 + c], ssum[c]);
            atomicAdd(&g_stats[D + cg * 8 + c], ssq[c]);
        }
    }
}

// ---------------- BN finalize (also re-zeroes stats for the next layer) ------
__global__ void k_finalize(const float* __restrict__ gamma, const float* __restrict__ beta) {
    int c = threadIdx.x;
    float mean = g_stats[c] * (1.f / NN);
    float var  = g_stats[D + c] * (1.f / NN) - mean * mean;  // biased var
    float sc   = gamma[c] * rsqrtf(var + BN_EPS);
    g_scale[c] = sc;
    g_shift[c] = fmaf(-mean, sc, beta[c]);
    g_stats[c] = 0.f;
    g_stats[D + c] = 0.f;
}

// ---------------- per-graph pooling (sorted batch -> contiguous ranges) ------
__global__ void k_pool(const float* __restrict__ h, int layer) {
    int g = blockIdx.x, t = threadIdx.x;
    int i0 = g_gstart[g], i1 = g_gstart[g + 1];
    float s0 = 0.f, s1 = 0.f, s2 = 0.f, s3 = 0.f;
    int i = i0;
    for (; i + 4 <= i1; i += 4) {
        s0 += h[(size_t)(i    ) * D + t];
        s1 += h[(size_t)(i + 1) * D + t];
        s2 += h[(size_t)(i + 2) * D + t];
        s3 += h[(size_t)(i + 3) * D + t];
    }
    for (; i < i1; i++) s0 += h[(size_t)i * D + t];
    g_pooled[(size_t)g * (4 * D) + layer * D + t] = (s0 + s1) + (s2 + s3);
}

// ---------------- classifier --------------------------------------------------
__global__ void k_cls1(const float* __restrict__ cw1, const float* __restrict__ cb1) {
    int g = blockIdx.x, c = threadIdx.x;     // 128 threads
    const float* p = g_pooled + (size_t)g * (4 * D);
    float s = cb1[c];
#pragma unroll 8
    for (int k = 0; k < 4 * D; k++) s = fmaf(p[k], cw1[(size_t)k * D + c], s);
    g_c1[g * D + c] = fmaxf(s, 0.f);
}

__global__ void k_cls2(const float* __restrict__ cw2, const float* __restrict__ cb2) {
    int g = blockIdx.x, c = threadIdx.x;     // 64 threads
    const float* p = g_c1 + g * D;
    float s = cb2[c];
#pragma unroll 8
    for (int k = 0; k < D; k++) s = fmaf(p[k], cw2[k * (D / 2) + c], s);
    g_c2[g * (D / 2) + c] = fmaxf(s, 0.f);
}

__global__ void k_cls3(const float* __restrict__ cw3, const float* __restrict__ cb3,
                       float* __restrict__ out) {
    int id = blockIdx.x * blockDim.x + threadIdx.x;
    if (id >= NG * 2) return;
    int g = id >> 1, c = id & 1;
    const float* p = g_c2 + g * (D / 2);
    float s = cb3[c];
#pragma unroll
    for (int k = 0; k < D / 2; k++) s = fmaf(p[k], cw3[k * 2 + c], s);
    out[id] = s;
}

// ---------------- launcher ----------------------------------------------------
extern "C" void kernel_launch(void* const* d_in, const int* in_sizes, int n_in,
                              void* d_out, int out_size) {
    const float* x    = (const float*)d_in[0];
    const int*   ei   = (const int*)  d_in[1];
    const int*   bat  = (const int*)  d_in[2];
    const float* w1   = (const float*)d_in[3];
    const float* b1   = (const float*)d_in[4];
    const float* g1   = (const float*)d_in[5];
    const float* be1  = (const float*)d_in[6];
    const float* w2   = (const float*)d_in[7];
    const float* b2   = (const float*)d_in[8];
    const float* lw1  = (const float*)d_in[9];
    const float* lb1  = (const float*)d_in[10];
    const float* lg1  = (const float*)d_in[11];
    const float* lbe1 = (const float*)d_in[12];
    const float* lw2  = (const float*)d_in[13];
    const float* lb2  = (const float*)d_in[14];
    const float* cw1  = (const float*)d_in[15];
    const float* cb1  = (const float*)d_in[16];
    const float* cw2  = (const float*)d_in[17];
    const float* cb2  = (const float*)d_in[18];
    const float* cw3  = (const float*)d_in[19];
    const float* cb3  = (const float*)d_in[20];
    const int* src = ei;
    const int* dst = ei + NE;

    float *pAgg, *pH1, *pHA, *pHB;
    cudaGetSymbolAddress((void**)&pAgg, g_agg);
    cudaGetSymbolAddress((void**)&pH1,  g_h1);
    cudaGetSymbolAddress((void**)&pHA,  g_hA);
    cudaGetSymbolAddress((void**)&pHB,  g_hB);

    // CSR by dst (rebuilt every call; deterministic)
    k_init<<<(NN + 255) / 256, 256>>>(bat);      // launch 0
    k_hist<<<2048, 256>>>(dst);                  // launch 1
    k_scan<<<1, 1024>>>();                       // launch 2
    k_scatter<<<2048, 256>>>(src, dst);          // launch 3

    const int GB = (NN + 127) / 128;   // 782 tiles
    const float* H = x;
    for (int l = 0; l < 4; l++) {
        const float *W1, *B1, *G, *BE, *W2, *B2;
        if (l == 0) { W1 = w1; B1 = b1; G = g1; BE = be1; W2 = w2; B2 = b2; }
        else {
            W1 = lw1 + (size_t)(l - 1) * D * D;  B1 = lb1 + (l - 1) * D;
            G  = lg1 + (l - 1) * D;              BE = lbe1 + (l - 1) * D;
            W2 = lw2 + (size_t)(l - 1) * D * D;  B2 = lb2 + (l - 1) * D;
        }
        k_agg<<<NN, 128>>>(H);                               // launch 4 (l=0)
        k_gemm<0><<<GB, 256>>>(pAgg, W1, B1, pH1);           // launch 5 (l=0) -> ncu target
        k_finalize<<<1, 128>>>(G, BE);
        float* Hout = (l & 1) ? pHB : pHA;
        k_gemm<1><<<GB, 256>>>(pH1, W2, B2, Hout);
        k_pool<<<NG, 128>>>(Hout, l);
        H = Hout;
    }

    k_cls1<<<NG, 128>>>(cw1, cb1);
    k_cls2<<<NG, 64>>>(cw2, cb2);
    k_cls3<<<8, 256>>>(cw3, cb3, (float*)d_out);
}

// round 5
// speedup vs baseline: 1.6691x; 1.6691x over previous
#include <cuda_runtime.h>

#define NN 100000
#define NE 3200000
#define NG 1024
#define D  128
#define BN_EPS 1e-5f

// ---------------- scratch (static device globals; no runtime alloc) ----------
__device__ float g_agg[(size_t)NN * D];   // hin = h + sum_neighbors
__device__ float g_h1 [(size_t)NN * D];   // pre-BN hidden
__device__ float g_hA [(size_t)NN * D];   // layer output ping
__device__ float g_hB [(size_t)NN * D];   // layer output pong
__device__ int   g_rowptr[NN + 1];
__device__ int   g_cnt[NN];               // histogram, then fill cursor
__device__ int   g_csrc[NE];              // CSR: src node ids grouped by dst
__device__ float g_stats[2 * D];          // col sum, col sumsq
__device__ float g_scale[D];
__device__ float g_shift[D];
__device__ float g_pooled[(size_t)NG * 4 * D];
__device__ int   g_gstart[NG + 1];
__device__ float g_c1[NG * D];
__device__ float g_c2[NG * (D / 2)];

// ---------------- CSR build ---------------------------------------------------
__global__ void k_hist(const int* __restrict__ dst) {
    for (int e = blockIdx.x * blockDim.x + threadIdx.x; e < NE; e += gridDim.x * blockDim.x)
        atomicAdd(&g_cnt[dst[e]], 1);
}

// scan + reset cursors + graph boundaries (batch sorted) in one block
__global__ void k_scan(const int* __restrict__ batch) {
    __shared__ int totals[1024];
    int t = threadIdx.x;
    const int CH = (NN + 1023) / 1024;   // 98
    int start = t * CH;
    int end   = start + CH; if (end > NN) end = NN;
    int s = 0;
    for (int i = start; i < end; i++) s += g_cnt[i];
    totals[t] = s;
    __syncthreads();
    if (t == 0) {
        int run = 0;
        for (int i = 0; i < 1024; i++) { int v = totals[i]; totals[i] = run; run += v; }
        g_rowptr[NN] = run;   // == NE
    }
    __syncthreads();
    int run = totals[t];
    for (int i = start; i < end; i++) {
        g_rowptr[i] = run; run += g_cnt[i];
        g_cnt[i] = 0;                       // reset cursor for scatter
    }
    // graph boundaries: g_gstart[t] for t in [0, NG), plus the sentinel
    {
        int lo = 0, hi = NN;
        while (lo < hi) { int mid = (lo + hi) >> 1; if (batch[mid] < t) lo = mid + 1; else hi = mid; }
        g_gstart[t] = lo;
        if (t == 0) g_gstart[NG] = NN;
    }
}

__global__ void k_scatter(const int* __restrict__ src, const int* __restrict__ dst) {
    for (int e = blockIdx.x * blockDim.x + threadIdx.x; e < NE; e += gridDim.x * blockDim.x) {
        int d = dst[e];
        int pos = g_rowptr[d] + atomicAdd(&g_cnt[d], 1);
        g_csrc[pos] = src[e];
    }
}

// ---------------- aggregation: hin[i] = h[i] + sum_{e in CSR(i)} h[src(e)] ----
// one warp per node, float4 per lane (whole 512B row per warp), 4 nodes/block
__global__ void k_agg(const float* __restrict__ h) {
    int node = blockIdx.x * 4 + (threadIdx.x >> 5);
    int lane = threadIdx.x & 31;
    if (node >= NN) return;
    int e0 = g_rowptr[node], e1 = g_rowptr[node + 1];

    float4 acc = *(const float4*)(h + (size_t)node * D + lane * 4);
    int e = e0;
    for (; e + 4 <= e1; e += 4) {
        int s0 = g_csrc[e], s1 = g_csrc[e + 1], s2 = g_csrc[e + 2], s3 = g_csrc[e + 3];
        float4 v0 = *(const float4*)(h + (size_t)s0 * D + lane * 4);
        float4 v1 = *(const float4*)(h + (size_t)s1 * D + lane * 4);
        float4 v2 = *(const float4*)(h + (size_t)s2 * D + lane * 4);
        float4 v3 = *(const float4*)(h + (size_t)s3 * D + lane * 4);
        acc.x += (v0.x + v1.x) + (v2.x + v3.x);
        acc.y += (v0.y + v1.y) + (v2.y + v3.y);
        acc.z += (v0.z + v1.z) + (v2.z + v3.z);
        acc.w += (v0.w + v1.w) + (v2.w + v3.w);
    }
    for (; e < e1; e++) {
        float4 v = *(const float4*)(h + (size_t)g_csrc[e] * D + lane * 4);
        acc.x += v.x; acc.y += v.y; acc.z += v.z; acc.w += v.w;
    }
    *(float4*)(g_agg + (size_t)node * D + lane * 4) = acc;
}

// ---------------- GEMM: C[M,128] = op(A)[M,128] @ W[128,128] + b --------------
// Proven round-3 core: 64x128 tile, 256 threads, 8 rows x 4 cols per thread.
// MODE 0: plain A, no output relu; fused BN statistics (col sum/sumsq -> g_stats)
// MODE 1: A' = relu(A*scale + shift) per column (fused BN+ReLU), output relu
template <int MODE>
__global__ void __launch_bounds__(256) k_gemm(const float* __restrict__ A,
                                              const float* __restrict__ W,
                                              const float* __restrict__ bias,
                                              float* __restrict__ C) {
    __shared__ float As[64][36];     // 64 rows x 32 K-cols (padded)
    __shared__ float Ws[32][128];    // 32 K-rows x 128 cols
    int tid = threadIdx.x;
    int tc = tid & 31;               // col group (4 cols)
    int tr = tid >> 5;               // row group (8 rows); constant within warp
    int m0 = blockIdx.x * 64;

    float acc[8][4];
#pragma unroll
    for (int r = 0; r < 8; r++)
#pragma unroll
        for (int c = 0; c < 4; c++) acc[r][c] = 0.f;

    for (int k0 = 0; k0 < D; k0 += 32) {
#pragma unroll
        for (int j = 0; j < 2; j++) {        // A tile: 512 float4, 2/thread
            int f = tid * 2 + j;
            int r = f >> 3, kq = f & 7;
            int row = m0 + r;
            float4 v = make_float4(0.f, 0.f, 0.f, 0.f);
            if (row < NN) v = *(const float4*)(A + (size_t)row * D + k0 + kq * 4);
            if (MODE == 1) {
                float4 sc = *(const float4*)(g_scale + k0 + kq * 4);
                float4 sh = *(const float4*)(g_shift + k0 + kq * 4);
                v.x = fmaxf(fmaf(v.x, sc.x, sh.x), 0.f);
                v.y = fmaxf(fmaf(v.y, sc.y, sh.y), 0.f);
                v.z = fmaxf(fmaf(v.z, sc.z, sh.z), 0.f);
                v.w = fmaxf(fmaf(v.w, sc.w, sh.w), 0.f);
            }
            *(float4*)&As[r][kq * 4] = v;
        }
#pragma unroll
        for (int j = 0; j < 4; j++) {        // W tile: 1024 float4, 4/thread
            int f = j * 256 + tid;
            int k = f >> 5, q = f & 31;
            *(float4*)&Ws[k][q * 4] = *(const float4*)(W + (size_t)(k0 + k) * D + q * 4);
        }
        __syncthreads();
#pragma unroll
        for (int k = 0; k < 32; k++) {
            float4 wv = *(const float4*)&Ws[k][tc * 4];
#pragma unroll
            for (int r = 0; r < 8; r++) {
                float a = As[tr * 8 + r][k];    // broadcast within warp
                acc[r][0] = fmaf(a, wv.x, acc[r][0]);
                acc[r][1] = fmaf(a, wv.y, acc[r][1]);
                acc[r][2] = fmaf(a, wv.z, acc[r][2]);
                acc[r][3] = fmaf(a, wv.w, acc[r][3]);
            }
        }
        __syncthreads();
    }

    float4 bv = *(const float4*)(bias + tc * 4);
    float ssum[4], ssq[4];
    if (MODE == 0) {
#pragma unroll
        for (int c = 0; c < 4; c++) { ssum[c] = 0.f; ssq[c] = 0.f; }
    }

#pragma unroll
    for (int r = 0; r < 8; r++) {
        int row = m0 + tr * 8 + r;
        if (row < NN) {
            float4 o;
            o.x = acc[r][0] + bv.x;
            o.y = acc[r][1] + bv.y;
            o.z = acc[r][2] + bv.z;
            o.w = acc[r][3] + bv.w;
            if (MODE == 1) {
                o.x = fmaxf(o.x, 0.f); o.y = fmaxf(o.y, 0.f);
                o.z = fmaxf(o.z, 0.f); o.w = fmaxf(o.w, 0.f);
            } else {
                ssum[0] += o.x; ssq[0] = fmaf(o.x, o.x, ssq[0]);
                ssum[1] += o.y; ssq[1] = fmaf(o.y, o.y, ssq[1]);
                ssum[2] += o.z; ssq[2] = fmaf(o.z, o.z, ssq[2]);
                ssum[3] += o.w; ssq[3] = fmaf(o.w, o.w, ssq[3]);
            }
            *(float4*)(C + (size_t)row * D + tc * 4) = o;
        }
    }

    if (MODE == 0) {
        // fused BN statistics: 8 no-return global reductions per thread
#pragma unroll
        for (int c = 0; c < 4; c++) {
            atomicAdd(&g_stats[tc * 4 + c], ssum[c]);
            atomicAdd(&g_stats[D + tc * 4 + c], ssq[c]);
        }
    }
}

// ---------------- BN finalize (also re-zeroes stats for the next layer) ------
__global__ void k_finalize(const float* __restrict__ gamma, const float* __restrict__ beta) {
    int c = threadIdx.x;
    float mean = g_stats[c] * (1.f / NN);
    float var  = g_stats[D + c] * (1.f / NN) - mean * mean;  // biased var
    float sc   = gamma[c] * rsqrtf(var + BN_EPS);
    g_scale[c] = sc;
    g_shift[c] = fmaf(-mean, sc, beta[c]);
    g_stats[c] = 0.f;
    g_stats[D + c] = 0.f;
}

// ---------------- per-graph pooling (sorted batch -> contiguous ranges) ------
__global__ void k_pool(const float* __restrict__ h, int layer) {
    int g = blockIdx.x, t = threadIdx.x;
    int i0 = g_gstart[g], i1 = g_gstart[g + 1];
    float s0 = 0.f, s1 = 0.f, s2 = 0.f, s3 = 0.f;
    int i = i0;
    for (; i + 4 <= i1; i += 4) {
        s0 += h[(size_t)(i    ) * D + t];
        s1 += h[(size_t)(i + 1) * D + t];
        s2 += h[(size_t)(i + 2) * D + t];
        s3 += h[(size_t)(i + 3) * D + t];
    }
    for (; i < i1; i++) s0 += h[(size_t)i * D + t];
    g_pooled[(size_t)g * (4 * D) + layer * D + t] = (s0 + s1) + (s2 + s3);
}

// ---------------- classifier --------------------------------------------------
__global__ void k_cls1(const float* __restrict__ cw1, const float* __restrict__ cb1) {
    int g = blockIdx.x, c = threadIdx.x;     // 128 threads
    const float* p = g_pooled + (size_t)g * (4 * D);
    float s = cb1[c];
#pragma unroll 8
    for (int k = 0; k < 4 * D; k++) s = fmaf(p[k], cw1[(size_t)k * D + c], s);
    g_c1[g * D + c] = fmaxf(s, 0.f);
}

__global__ void k_cls2(const float* __restrict__ cw2, const float* __restrict__ cb2) {
    int g = blockIdx.x, c = threadIdx.x;     // 64 threads
    const float* p = g_c1 + g * D;
    float s = cb2[c];
#pragma unroll 8
    for (int k = 0; k < D; k++) s = fmaf(p[k], cw2[k * (D / 2) + c], s);
    g_c2[g * (D / 2) + c] = fmaxf(s, 0.f);
}

__global__ void k_cls3(const float* __restrict__ cw3, const float* __restrict__ cb3,
                       float* __restrict__ out) {
    int id = blockIdx.x * blockDim.x + threadIdx.x;
    if (id >= NG * 2) return;
    int g = id >> 1, c = id & 1;
    const float* p = g_c2 + g * (D / 2);
    float s = cb3[c];
#pragma unroll
    for (int k = 0; k < D / 2; k++) s = fmaf(p[k], cw3[k * 2 + c], s);
    out[id] = s;
}

// ---------------- launcher ----------------------------------------------------
extern "C" void kernel_launch(void* const* d_in, const int* in_sizes, int n_in,
                              void* d_out, int out_size) {
    const float* x    = (const float*)d_in[0];
    const int*   ei   = (const int*)  d_in[1];
    const int*   bat  = (const int*)  d_in[2];
    const float* w1   = (const float*)d_in[3];
    const float* b1   = (const float*)d_in[4];
    const float* g1   = (const float*)d_in[5];
    const float* be1  = (const float*)d_in[6];
    const float* w2   = (const float*)d_in[7];
    const float* b2   = (const float*)d_in[8];
    const float* lw1  = (const float*)d_in[9];
    const float* lb1  = (const float*)d_in[10];
    const float* lg1  = (const float*)d_in[11];
    const float* lbe1 = (const float*)d_in[12];
    const float* lw2  = (const float*)d_in[13];
    const float* lb2  = (const float*)d_in[14];
    const float* cw1  = (const float*)d_in[15];
    const float* cb1  = (const float*)d_in[16];
    const float* cw2  = (const float*)d_in[17];
    const float* cb2  = (const float*)d_in[18];
    const float* cw3  = (const float*)d_in[19];
    const float* cb3  = (const float*)d_in[20];
    const int* src = ei;
    const int* dst = ei + NE;

    float *pAgg, *pH1, *pHA, *pHB;
    int   *pCnt;
    float *pStats;
    cudaGetSymbolAddress((void**)&pAgg,   g_agg);
    cudaGetSymbolAddress((void**)&pH1,    g_h1);
    cudaGetSymbolAddress((void**)&pHA,    g_hA);
    cudaGetSymbolAddress((void**)&pHB,    g_hB);
    cudaGetSymbolAddress((void**)&pCnt,   g_cnt);
    cudaGetSymbolAddress((void**)&pStats, g_stats);

    // zero cnt + stats via memset nodes (no kernel launch slots consumed)
    cudaMemsetAsync(pCnt,   0, (size_t)NN * sizeof(int));
    cudaMemsetAsync(pStats, 0, 2 * D * sizeof(float));

    // CSR by dst (rebuilt every call; deterministic inputs)
    k_hist<<<2048, 256>>>(dst);                  // launch 0
    k_scan<<<1, 1024>>>(bat);                    // launch 1
    k_scatter<<<2048, 256>>>(src, dst);          // launch 2

    const int GB = (NN + 63) / 64;   // 1563 tiles
    const float* H = x;
    for (int l = 0; l < 4; l++) {
        const float *W1, *B1, *G, *BE, *W2, *B2;
        if (l == 0) { W1 = w1; B1 = b1; G = g1; BE = be1; W2 = w2; B2 = b2; }
        else {
            W1 = lw1 + (size_t)(l - 1) * D * D;  B1 = lb1 + (l - 1) * D;
            G  = lg1 + (l - 1) * D;              BE = lbe1 + (l - 1) * D;
            W2 = lw2 + (size_t)(l - 1) * D * D;  B2 = lb2 + (l - 1) * D;
        }
        k_agg<<<(NN + 3) / 4, 128>>>(H);                     // launch 3 (l=0) -> ncu slot
        k_gemm<0><<<GB, 256>>>(pAgg, W1, B1, pH1);           // launch 4 (l=0)
        k_finalize<<<1, 128>>>(G, BE);
        float* Hout = (l & 1) ? pHB : pHA;
        k_gemm<1><<<GB, 256>>>(pH1, W2, B2, Hout);
        k_pool<<<NG, 128>>>(Hout, l);
        H = Hout;
    }

    k_cls1<<<NG, 128>>>(cw1, cb1);
    k_cls2<<<NG, 64>>>(cw2, cb2);
    k_cls3<<<8, 256>>>(cw3, cb3, (float*)d_out);
}

// round 6
// speedup vs baseline: 1.6902x; 1.0126x over previous
#include <cuda_runtime.h>

#define NN 100000
#define NE 3200000
#define NG 1024
#define D  128
#define BN_EPS 1e-5f

// ---------------- scratch (static device globals; no runtime alloc) ----------
__device__ float g_agg[(size_t)NN * D];   // hin = h + sum_neighbors
__device__ float g_h1 [(size_t)NN * D];   // pre-BN hidden
__device__ float g_hA [(size_t)NN * D];   // layer output ping
__device__ float g_hB [(size_t)NN * D];   // layer output pong
__device__ int   g_rowptr[NN + 1];
__device__ int   g_cnt[NN];               // histogram, then fill cursor
__device__ int   g_csrc[NE];              // CSR: src node ids grouped by dst
// BN stats, one 128B line per scalar: [c*32] = sum(col c), [(128+c)*32] = sumsq(col c)
__device__ float g_stats2[256 * 32];
__device__ float g_scale[D];
__device__ float g_shift[D];
__device__ float g_pooled[(size_t)NG * 4 * D];
__device__ int   g_gstart[NG + 1];
__device__ float g_c1[NG * D];
__device__ float g_c2[NG * (D / 2)];

// ---------------- CSR build ---------------------------------------------------
__global__ void k_hist(const int* __restrict__ dst) {
    for (int e = blockIdx.x * blockDim.x + threadIdx.x; e < NE; e += gridDim.x * blockDim.x)
        atomicAdd(&g_cnt[dst[e]], 1);
}

// scan + reset cursors + graph boundaries (batch sorted) in one block
__global__ void k_scan(const int* __restrict__ batch) {
    __shared__ int totals[1024];
    int t = threadIdx.x;
    const int CH = (NN + 1023) / 1024;   // 98
    int start = t * CH;
    int end   = start + CH; if (end > NN) end = NN;
    int s = 0;
    for (int i = start; i < end; i++) s += g_cnt[i];
    totals[t] = s;
    __syncthreads();
    if (t == 0) {
        int run = 0;
        for (int i = 0; i < 1024; i++) { int v = totals[i]; totals[i] = run; run += v; }
        g_rowptr[NN] = run;   // == NE
    }
    __syncthreads();
    int run = totals[t];
    for (int i = start; i < end; i++) {
        g_rowptr[i] = run; run += g_cnt[i];
        g_cnt[i] = 0;                       // reset cursor for scatter
    }
    // graph boundaries: batch is sorted
    {
        int lo = 0, hi = NN;
        while (lo < hi) { int mid = (lo + hi) >> 1; if (batch[mid] < t) lo = mid + 1; else hi = mid; }
        g_gstart[t] = lo;
        if (t == 0) g_gstart[NG] = NN;
    }
}

__global__ void k_scatter(const int* __restrict__ src, const int* __restrict__ dst) {
    for (int e = blockIdx.x * blockDim.x + threadIdx.x; e < NE; e += gridDim.x * blockDim.x) {
        int d = dst[e];
        int pos = g_rowptr[d] + atomicAdd(&g_cnt[d], 1);
        g_csrc[pos] = src[e];
    }
}

// ---------------- aggregation: hin[i] = h[i] + sum_{e in CSR(i)} h[src(e)] ----
// one warp per node, float4 per lane (whole 512B row per warp), 4 nodes/block
__global__ void k_agg(const float* __restrict__ h) {
    int node = blockIdx.x * 4 + (threadIdx.x >> 5);
    int lane = threadIdx.x & 31;
    if (node >= NN) return;
    int e0 = g_rowptr[node], e1 = g_rowptr[node + 1];

    float4 acc = *(const float4*)(h + (size_t)node * D + lane * 4);
    int e = e0;
    for (; e + 4 <= e1; e += 4) {
        int s0 = g_csrc[e], s1 = g_csrc[e + 1], s2 = g_csrc[e + 2], s3 = g_csrc[e + 3];
        float4 v0 = *(const float4*)(h + (size_t)s0 * D + lane * 4);
        float4 v1 = *(const float4*)(h + (size_t)s1 * D + lane * 4);
        float4 v2 = *(const float4*)(h + (size_t)s2 * D + lane * 4);
        float4 v3 = *(const float4*)(h + (size_t)s3 * D + lane * 4);
        acc.x += (v0.x + v1.x) + (v2.x + v3.x);
        acc.y += (v0.y + v1.y) + (v2.y + v3.y);
        acc.z += (v0.z + v1.z) + (v2.z + v3.z);
        acc.w += (v0.w + v1.w) + (v2.w + v3.w);
    }
    for (; e < e1; e++) {
        float4 v = *(const float4*)(h + (size_t)g_csrc[e] * D + lane * 4);
        acc.x += v.x; acc.y += v.y; acc.z += v.z; acc.w += v.w;
    }
    *(float4*)(g_agg + (size_t)node * D + lane * 4) = acc;
}

// ---------------- GEMM: C[M,128] = op(A)[M,128] @ W[128,128] + b --------------
// 64x128 tile, 256 threads, 8 rows x 4 cols per thread, register-prefetch pipeline.
// MODE 0: plain A, no output relu; fused BN statistics (smem block-reduce -> line-spread REDs)
// MODE 1: A' = relu(A*scale + shift) per column (fused BN+ReLU), output relu
template <int MODE>
__global__ void __launch_bounds__(256) k_gemm(const float* __restrict__ A,
                                              const float* __restrict__ W,
                                              const float* __restrict__ bias,
                                              float* __restrict__ C) {
    __shared__ float As[64][36];     // 64 rows x 32 K-cols (padded)
    __shared__ float Ws[32][128];    // 32 K-rows x 128 cols
    __shared__ float redS[8][132];   // per-tr partial col sums (padded stride)
    __shared__ float redQ[8][132];   // per-tr partial col sumsqs
    const int tid = threadIdx.x;
    const int tc = tid & 31;               // col group (4 cols)
    const int tr = tid >> 5;               // row group (8 rows); constant within warp
    const int m0 = blockIdx.x * 64;

    // per-thread A-load coords are tile-invariant
    const int ar0 = (tid * 2)     >> 3, akq0 = (tid * 2)     & 7;
    const int ar1 = (tid * 2 + 1) >> 3, akq1 = (tid * 2 + 1) & 7;

    float acc[8][4];
#pragma unroll
    for (int r = 0; r < 8; r++)
#pragma unroll
        for (int c = 0; c < 4; c++) acc[r][c] = 0.f;

    float4 pa[2], pw[4];

    // ---- prefetch helpers -----------------------------------------------
    auto loadA = [&](int k0) {
#pragma unroll
        for (int j = 0; j < 2; j++) {
            int r  = j ? ar1 : ar0;
            int kq = j ? akq1 : akq0;
            int row = m0 + r;
            float4 v = make_float4(0.f, 0.f, 0.f, 0.f);
            if (row < NN) v = *(const float4*)(A + (size_t)row * D + k0 + kq * 4);
            if (MODE == 1) {
                float4 sc = *(const float4*)(g_scale + k0 + kq * 4);
                float4 sh = *(const float4*)(g_shift + k0 + kq * 4);
                v.x = fmaxf(fmaf(v.x, sc.x, sh.x), 0.f);
                v.y = fmaxf(fmaf(v.y, sc.y, sh.y), 0.f);
                v.z = fmaxf(fmaf(v.z, sc.z, sh.z), 0.f);
                v.w = fmaxf(fmaf(v.w, sc.w, sh.w), 0.f);
            }
            pa[j] = v;
        }
    };
    auto loadW = [&](int k0) {
#pragma unroll
        for (int j = 0; j < 4; j++) {
            int f = j * 256 + tid;
            int k = f >> 5, q = f & 31;
            pw[j] = *(const float4*)(W + (size_t)(k0 + k) * D + q * 4);
        }
    };

    loadA(0); loadW(0);

#pragma unroll
    for (int t = 0; t < 4; t++) {
        // store prefetched tile into smem
        *(float4*)&As[ar0][akq0 * 4] = pa[0];
        *(float4*)&As[ar1][akq1 * 4] = pa[1];
#pragma unroll
        for (int j = 0; j < 4; j++) {
            int f = j * 256 + tid;
            int k = f >> 5, q = f & 31;
            *(float4*)&Ws[k][q * 4] = pw[j];
        }
        __syncthreads();
        if (t < 3) { loadA((t + 1) * 32); loadW((t + 1) * 32); }   // hide behind compute
#pragma unroll
        for (int k = 0; k < 32; k++) {
            float4 wv = *(const float4*)&Ws[k][tc * 4];
#pragma unroll
            for (int r = 0; r < 8; r++) {
                float a = As[tr * 8 + r][k];    // broadcast within warp
                acc[r][0] = fmaf(a, wv.x, acc[r][0]);
                acc[r][1] = fmaf(a, wv.y, acc[r][1]);
                acc[r][2] = fmaf(a, wv.z, acc[r][2]);
                acc[r][3] = fmaf(a, wv.w, acc[r][3]);
            }
        }
        __syncthreads();
    }

    float4 bv = *(const float4*)(bias + tc * 4);
    float ssum[4], ssq[4];
    if (MODE == 0) {
#pragma unroll
        for (int c = 0; c < 4; c++) { ssum[c] = 0.f; ssq[c] = 0.f; }
    }

#pragma unroll
    for (int r = 0; r < 8; r++) {
        int row = m0 + tr * 8 + r;
        if (row < NN) {
            float4 o;
            o.x = acc[r][0] + bv.x;
            o.y = acc[r][1] + bv.y;
            o.z = acc[r][2] + bv.z;
            o.w = acc[r][3] + bv.w;
            if (MODE == 1) {
                o.x = fmaxf(o.x, 0.f); o.y = fmaxf(o.y, 0.f);
                o.z = fmaxf(o.z, 0.f); o.w = fmaxf(o.w, 0.f);
            } else {
                ssum[0] += o.x; ssq[0] = fmaf(o.x, o.x, ssq[0]);
                ssum[1] += o.y; ssq[1] = fmaf(o.y, o.y, ssq[1]);
                ssum[2] += o.z; ssq[2] = fmaf(o.z, o.z, ssq[2]);
                ssum[3] += o.w; ssq[3] = fmaf(o.w, o.w, ssq[3]);
            }
            *(float4*)(C + (size_t)row * D + tc * 4) = o;
        }
    }

    if (MODE == 0) {
        // block-level reduction in smem, then 256 line-spread global REDs
#pragma unroll
        for (int c = 0; c < 4; c++) {
            redS[tr][tc * 4 + c] = ssum[c];
            redQ[tr][tc * 4 + c] = ssq[c];
        }
        __syncthreads();
        if (tid < 128) {
            float s = 0.f;
#pragma unroll
            for (int j = 0; j < 8; j++) s += redS[j][tid];
            atomicAdd(&g_stats2[tid * 32], s);
        } else {
            int c = tid - 128;
            float q = 0.f;
#pragma unroll
            for (int j = 0; j < 8; j++) q += redQ[j][c];
            atomicAdd(&g_stats2[(128 + c) * 32], q);
        }
    }
}

// ---------------- BN finalize (also re-zeroes stats for the next layer) ------
__global__ void k_finalize(const float* __restrict__ gamma, const float* __restrict__ beta) {
    int c = threadIdx.x;
    float mean = g_stats2[c * 32] * (1.f / NN);
    float var  = g_stats2[(128 + c) * 32] * (1.f / NN) - mean * mean;  // biased var
    float sc   = gamma[c] * rsqrtf(var + BN_EPS);
    g_scale[c] = sc;
    g_shift[c] = fmaf(-mean, sc, beta[c]);
    g_stats2[c * 32] = 0.f;
    g_stats2[(128 + c) * 32] = 0.f;
}

// ---------------- per-graph pooling (sorted batch -> contiguous ranges) ------
__global__ void k_pool(const float* __restrict__ h, int layer) {
    int g = blockIdx.x, t = threadIdx.x;
    int i0 = g_gstart[g], i1 = g_gstart[g + 1];
    float s0 = 0.f, s1 = 0.f, s2 = 0.f, s3 = 0.f;
    int i = i0;
    for (; i + 4 <= i1; i += 4) {
        s0 += h[(size_t)(i    ) * D + t];
        s1 += h[(size_t)(i + 1) * D + t];
        s2 += h[(size_t)(i + 2) * D + t];
        s3 += h[(size_t)(i + 3) * D + t];
    }
    for (; i < i1; i++) s0 += h[(size_t)i * D + t];
    g_pooled[(size_t)g * (4 * D) + layer * D + t] = (s0 + s1) + (s2 + s3);
}

// ---------------- classifier --------------------------------------------------
__global__ void k_cls1(const float* __restrict__ cw1, const float* __restrict__ cb1) {
    int g = blockIdx.x, c = threadIdx.x;     // 128 threads
    const float* p = g_pooled + (size_t)g * (4 * D);
    float s = cb1[c];
#pragma unroll 8
    for (int k = 0; k < 4 * D; k++) s = fmaf(p[k], cw1[(size_t)k * D + c], s);
    g_c1[g * D + c] = fmaxf(s, 0.f);
}

__global__ void k_cls2(const float* __restrict__ cw2, const float* __restrict__ cb2) {
    int g = blockIdx.x, c = threadIdx.x;     // 64 threads
    const float* p = g_c1 + g * D;
    float s = cb2[c];
#pragma unroll 8
    for (int k = 0; k < D; k++) s = fmaf(p[k], cw2[k * (D / 2) + c], s);
    g_c2[g * (D / 2) + c] = fmaxf(s, 0.f);
}

__global__ void k_cls3(const float* __restrict__ cw3, const float* __restrict__ cb3,
                       float* __restrict__ out) {
    int id = blockIdx.x * blockDim.x + threadIdx.x;
    if (id >= NG * 2) return;
    int g = id >> 1, c = id & 1;
    const float* p = g_c2 + g * (D / 2);
    float s = cb3[c];
#pragma unroll
    for (int k = 0; k < D / 2; k++) s = fmaf(p[k], cw3[k * 2 + c], s);
    out[id] = s;
}

// ---------------- launcher ----------------------------------------------------
extern "C" void kernel_launch(void* const* d_in, const int* in_sizes, int n_in,
                              void* d_out, int out_size) {
    const float* x    = (const float*)d_in[0];
    const int*   ei   = (const int*)  d_in[1];
    const int*   bat  = (const int*)  d_in[2];
    const float* w1   = (const float*)d_in[3];
    const float* b1   = (const float*)d_in[4];
    const float* g1   = (const float*)d_in[5];
    const float* be1  = (const float*)d_in[6];
    const float* w2   = (const float*)d_in[7];
    const float* b2   = (const float*)d_in[8];
    const float* lw1  = (const float*)d_in[9];
    const float* lb1  = (const float*)d_in[10];
    const float* lg1  = (const float*)d_in[11];
    const float* lbe1 = (const float*)d_in[12];
    const float* lw2  = (const float*)d_in[13];
    const float* lb2  = (const float*)d_in[14];
    const float* cw1  = (const float*)d_in[15];
    const float* cb1  = (const float*)d_in[16];
    const float* cw2  = (const float*)d_in[17];
    const float* cb2  = (const float*)d_in[18];
    const float* cw3  = (const float*)d_in[19];
    const float* cb3  = (const float*)d_in[20];
    const int* src = ei;
    const int* dst = ei + NE;

    float *pAgg, *pH1, *pHA, *pHB, *pStats;
    int   *pCnt;
    cudaGetSymbolAddress((void**)&pAgg,   g_agg);
    cudaGetSymbolAddress((void**)&pH1,    g_h1);
    cudaGetSymbolAddress((void**)&pHA,    g_hA);
    cudaGetSymbolAddress((void**)&pHB,    g_hB);
    cudaGetSymbolAddress((void**)&pCnt,   g_cnt);
    cudaGetSymbolAddress((void**)&pStats, g_stats2);

    cudaMemsetAsync(pCnt,   0, (size_t)NN * sizeof(int));
    cudaMemsetAsync(pStats, 0, 256 * 32 * sizeof(float));

    // CSR by dst (rebuilt every call; deterministic inputs)
    k_hist<<<2048, 256>>>(dst);                  // launch 0
    k_scan<<<1, 1024>>>(bat);                    // launch 1
    k_scatter<<<2048, 256>>>(src, dst);          // launch 2

    const int GB = (NN + 63) / 64;   // 1563 tiles
    const float* H = x;
    for (int l = 0; l < 4; l++) {
        const float *W1, *B1, *G, *BE, *W2, *B2;
        if (l == 0) { W1 = w1; B1 = b1; G = g1; BE = be1; W2 = w2; B2 = b2; }
        else {
            W1 = lw1 + (size_t)(l - 1) * D * D;  B1 = lb1 + (l - 1) * D;
            G  = lg1 + (l - 1) * D;              BE = lbe1 + (l - 1) * D;
            W2 = lw2 + (size_t)(l - 1) * D * D;  B2 = lb2 + (l - 1) * D;
        }
        k_agg<<<(NN + 3) / 4, 128>>>(H);                     // launch 3 (l=0)
        k_gemm<0><<<GB, 256>>>(pAgg, W1, B1, pH1);           // launch 4 (l=0) -> ncu slot
        k_finalize<<<1, 128>>>(G, BE);
        float* Hout = (l & 1) ? pHB : pHA;
        k_gemm<1><<<GB, 256>>>(pH1, W2, B2, Hout);
        k_pool<<<NG, 128>>>(Hout, l);
        H = Hout;
    }

    k_cls1<<<NG, 128>>>(cw1, cb1);
    k_cls2<<<NG, 64>>>(cw2, cb2);
    k_cls3<<<8, 256>>>(cw3, cb3, (float*)d_out);
}

// round 8
// speedup vs baseline: 3.1406x; 1.8582x over previous
#include <cuda_runtime.h>
#include <cuda_bf16.h>

#define NN 100000
#define NE 3200000
#define NG 1024
#define D  128
#define BN_EPS 1e-5f

// ---------------- scratch (static device globals; no runtime alloc) ----------
__device__ float g_agg[(size_t)NN * D];   // hin = h + sum_neighbors
__device__ float g_h1 [(size_t)NN * D];   // pre-BN hidden
__device__ float g_hA [(size_t)NN * D];   // layer output ping
__device__ float g_hB [(size_t)NN * D];   // layer output pong
__device__ int   g_rowptr[NN + 1];
__device__ int   g_cnt[NN];               // histogram, then fill cursor
__device__ int   g_csrc[NE];              // CSR: src node ids grouped by dst
// BN stats, one 128B line per scalar: [c*32] = sum(col c), [(128+c)*32] = sumsq(col c)
__device__ float g_stats2[256 * 32];
__device__ float g_scale[D];
__device__ float g_shift[D];
__device__ float g_pooled[(size_t)NG * 4 * D];
__device__ int   g_gstart[NG + 1];
__device__ float g_c1[NG * D];
__device__ float g_c2[NG * (D / 2)];

// ---------------- mma/ldmatrix helpers ----------------------------------------
__device__ __forceinline__ unsigned smem_u32(const void* p) {
    return (unsigned)__cvta_generic_to_shared(p);
}
__device__ __forceinline__ void ldsm_x4(unsigned addr, unsigned& r0, unsigned& r1,
                                        unsigned& r2, unsigned& r3) {
    asm volatile("ldmatrix.sync.aligned.m8n8.x4.shared.b16 {%0,%1,%2,%3}, [%4];"
                 : "=r"(r0), "=r"(r1), "=r"(r2), "=r"(r3) : "r"(addr));
}
__device__ __forceinline__ void ldsm_x4t(unsigned addr, unsigned& r0, unsigned& r1,
                                         unsigned& r2, unsigned& r3) {
    asm volatile("ldmatrix.sync.aligned.m8n8.x4.trans.shared.b16 {%0,%1,%2,%3}, [%4];"
                 : "=r"(r0), "=r"(r1), "=r"(r2), "=r"(r3) : "r"(addr));
}
__device__ __forceinline__ void mma_bf16(float* d, const unsigned* a, const unsigned* b) {
    asm volatile(
        "mma.sync.aligned.m16n8k16.row.col.f32.bf16.bf16.f32 "
        "{%0,%1,%2,%3}, {%4,%5,%6,%7}, {%8,%9}, {%0,%1,%2,%3};"
        : "+f"(d[0]), "+f"(d[1]), "+f"(d[2]), "+f"(d[3])
        : "r"(a[0]), "r"(a[1]), "r"(a[2]), "r"(a[3]), "r"(b[0]), "r"(b[1]));
}
__device__ __forceinline__ void split_bf16(float v, __nv_bfloat16& h, __nv_bfloat16& l) {
    h = __float2bfloat16_rn(v);
    l = __float2bfloat16_rn(v - __bfloat162float(h));
}

// ---------------- CSR build ---------------------------------------------------
__global__ void k_hist(const int* __restrict__ dst) {
    for (int e = blockIdx.x * blockDim.x + threadIdx.x; e < NE; e += gridDim.x * blockDim.x)
        atomicAdd(&g_cnt[dst[e]], 1);
}

// scan + reset cursors + graph boundaries (batch sorted) in one block
__global__ void k_scan(const int* __restrict__ batch) {
    __shared__ int totals[1024];
    int t = threadIdx.x;
    const int CH = (NN + 1023) / 1024;   // 98
    int start = t * CH;
    int end   = start + CH; if (end > NN) end = NN;
    int s = 0;
    for (int i = start; i < end; i++) s += g_cnt[i];
    totals[t] = s;
    __syncthreads();
    if (t == 0) {
        int run = 0;
        for (int i = 0; i < 1024; i++) { int v = totals[i]; totals[i] = run; run += v; }
        g_rowptr[NN] = run;   // == NE
    }
    __syncthreads();
    int run = totals[t];
    for (int i = start; i < end; i++) {
        g_rowptr[i] = run; run += g_cnt[i];
        g_cnt[i] = 0;                       // reset cursor for scatter
    }
    {
        int lo = 0, hi = NN;
        while (lo < hi) { int mid = (lo + hi) >> 1; if (batch[mid] < t) lo = mid + 1; else hi = mid; }
        g_gstart[t] = lo;
        if (t == 0) g_gstart[NG] = NN;
    }
}

__global__ void k_scatter(const int* __restrict__ src, const int* __restrict__ dst) {
    for (int e = blockIdx.x * blockDim.x + threadIdx.x; e < NE; e += gridDim.x * blockDim.x) {
        int d = dst[e];
        int pos = g_rowptr[d] + atomicAdd(&g_cnt[d], 1);
        g_csrc[pos] = src[e];
    }
}

// ---------------- aggregation (proven: warp per node, float4 lanes) ----------
__global__ void k_agg(const float* __restrict__ h) {
    int node = blockIdx.x * 4 + (threadIdx.x >> 5);
    int lane = threadIdx.x & 31;
    if (node >= NN) return;
    int e0 = g_rowptr[node], e1 = g_rowptr[node + 1];

    float4 acc = *(const float4*)(h + (size_t)node * D + lane * 4);
    int e = e0;
    for (; e + 4 <= e1; e += 4) {
        int s0 = g_csrc[e], s1 = g_csrc[e + 1], s2 = g_csrc[e + 2], s3 = g_csrc[e + 3];
        float4 v0 = *(const float4*)(h + (size_t)s0 * D + lane * 4);
        float4 v1 = *(const float4*)(h + (size_t)s1 * D + lane * 4);
        float4 v2 = *(const float4*)(h + (size_t)s2 * D + lane * 4);
        float4 v3 = *(const float4*)(h + (size_t)s3 * D + lane * 4);
        acc.x += (v0.x + v1.x) + (v2.x + v3.x);
        acc.y += (v0.y + v1.y) + (v2.y + v3.y);
        acc.z += (v0.z + v1.z) + (v2.z + v3.z);
        acc.w += (v0.w + v1.w) + (v2.w + v3.w);
    }
    for (; e < e1; e++) {
        float4 v = *(const float4*)(h + (size_t)g_csrc[e] * D + lane * 4);
        acc.x += v.x; acc.y += v.y; acc.z += v.z; acc.w += v.w;
    }
    *(float4*)(g_agg + (size_t)node * D + lane * 4) = acc;
}

// ---------------- tensor-core GEMM: C = op(A)[M,128] @ W[128,128] + b ---------
// 128x128 block tile, 256 threads (8 warps, warp tile 32x64), bf16 2-way split,
// 3-term mma (hi*hi + hi*lo + lo*hi), fp32 accumulate.
// MODE 0: plain A, no output relu. MODE 1: A'=relu(A*scale+shift), relu output.
template <int MODE>
__global__ void __launch_bounds__(256) k_gemm_tc(const float* __restrict__ A,
                                                 const float* __restrict__ W,
                                                 const float* __restrict__ bias,
                                                 float* __restrict__ C) {
    constexpr int AP = 40;    // A smem pitch in bf16 (80B: conflict-free ldmatrix)
    constexpr int BP = 136;   // B smem pitch in bf16 (272B: conflict-free ldmatrix)
    __shared__ __nv_bfloat16 a_hi[128 * AP], a_lo[128 * AP];
    __shared__ __nv_bfloat16 b_hi[32 * BP],  b_lo[32 * BP];

    const int tid  = threadIdx.x;
    const int lane = tid & 31;
    const int warp = tid >> 5;
    const int wm = (warp >> 1) * 32;     // warp row base: 0/32/64/96
    const int wn = (warp & 1) * 64;      // warp col base: 0/64
    const int m0 = blockIdx.x * 128;

    float acc[2][8][4];
#pragma unroll
    for (int mf = 0; mf < 2; mf++)
#pragma unroll
        for (int nf = 0; nf < 8; nf++)
#pragma unroll
            for (int i = 0; i < 4; i++) acc[mf][nf][i] = 0.f;

    // ldmatrix source coords (canonical group->operand order)
    const int a_row = (lane & 7) + ((lane >> 3) & 1) * 8;  // +mf*16
    const int a_kof = (lane >> 4) * 8;                      // +ks
    const int b_kof = (lane & 7) + ((lane >> 3) & 1) * 8;   // +ks
    const int b_nof = (lane >> 4) * 8;                      // +wn+ng*16

    for (int k0 = 0; k0 < D; k0 += 32) {
        // stage + split A chunk [128 x 32]
#pragma unroll
        for (int j = 0; j < 4; j++) {
            int f = j * 256 + tid;
            int r = f >> 3, kq = f & 7;
            int row = m0 + r;
            float4 v = make_float4(0.f, 0.f, 0.f, 0.f);
            if (row < NN) v = *(const float4*)(A + (size_t)row * D + k0 + kq * 4);
            if (MODE == 1) {
                float4 sc = *(const float4*)(g_scale + k0 + kq * 4);
                float4 sh = *(const float4*)(g_shift + k0 + kq * 4);
                v.x = fmaxf(fmaf(v.x, sc.x, sh.x), 0.f);
                v.y = fmaxf(fmaf(v.y, sc.y, sh.y), 0.f);
                v.z = fmaxf(fmaf(v.z, sc.z, sh.z), 0.f);
                v.w = fmaxf(fmaf(v.w, sc.w, sh.w), 0.f);
            }
            __nv_bfloat16 h0, h1, h2, h3, l0, l1, l2, l3;
            split_bf16(v.x, h0, l0); split_bf16(v.y, h1, l1);
            split_bf16(v.z, h2, l2); split_bf16(v.w, h3, l3);
            __nv_bfloat162* ph = (__nv_bfloat162*)(a_hi + r * AP + kq * 4);
            __nv_bfloat162* pl = (__nv_bfloat162*)(a_lo + r * AP + kq * 4);
            ph[0] = __nv_bfloat162(h0, h1); ph[1] = __nv_bfloat162(h2, h3);
            pl[0] = __nv_bfloat162(l0, l1); pl[1] = __nv_bfloat162(l2, l3);
        }
        // stage + split W chunk [32 x 128]
#pragma unroll
        for (int j = 0; j < 4; j++) {
            int f = j * 256 + tid;
            int k = f >> 5, q = f & 31;
            float4 v = *(const float4*)(W + (size_t)(k0 + k) * D + q * 4);
            __nv_bfloat16 h0, h1, h2, h3, l0, l1, l2, l3;
            split_bf16(v.x, h0, l0); split_bf16(v.y, h1, l1);
            split_bf16(v.z, h2, l2); split_bf16(v.w, h3, l3);
            __nv_bfloat162* ph = (__nv_bfloat162*)(b_hi + k * BP + q * 4);
            __nv_bfloat162* pl = (__nv_bfloat162*)(b_lo + k * BP + q * 4);
            ph[0] = __nv_bfloat162(h0, h1); ph[1] = __nv_bfloat162(h2, h3);
            pl[0] = __nv_bfloat162(l0, l1); pl[1] = __nv_bfloat162(l2, l3);
        }
        __syncthreads();

#pragma unroll
        for (int ks = 0; ks < 32; ks += 16) {
            unsigned afh[2][4], afl[2][4];
#pragma unroll
            for (int mf = 0; mf < 2; mf++) {
                unsigned ah = smem_u32(a_hi + (wm + mf * 16 + a_row) * AP + ks + a_kof);
                unsigned al = smem_u32(a_lo + (wm + mf * 16 + a_row) * AP + ks + a_kof);
                ldsm_x4(ah, afh[mf][0], afh[mf][1], afh[mf][2], afh[mf][3]);
                ldsm_x4(al, afl[mf][0], afl[mf][1], afl[mf][2], afl[mf][3]);
            }
#pragma unroll
            for (int ng = 0; ng < 4; ng++) {      // 2 n-frags per group
                unsigned bh[4], bl[4];
                int bc = wn + ng * 16 + b_nof;
                ldsm_x4t(smem_u32(b_hi + (ks + b_kof) * BP + bc), bh[0], bh[1], bh[2], bh[3]);
                ldsm_x4t(smem_u32(b_lo + (ks + b_kof) * BP + bc), bl[0], bl[1], bl[2], bl[3]);
#pragma unroll
                for (int mf = 0; mf < 2; mf++) {
                    mma_bf16(acc[mf][2 * ng],     afh[mf], bh);
                    mma_bf16(acc[mf][2 * ng],     afh[mf], bl);
                    mma_bf16(acc[mf][2 * ng],     afl[mf], bh);
                    mma_bf16(acc[mf][2 * ng + 1], afh[mf], bh + 2);
                    mma_bf16(acc[mf][2 * ng + 1], afh[mf], bl + 2);
                    mma_bf16(acc[mf][2 * ng + 1], afl[mf], bh + 2);
                }
            }
        }
        __syncthreads();
    }

    // epilogue: acc frag (m16n8): c0/c1 -> row g, cols c,c+1; c2/c3 -> row g+8
#pragma unroll
    for (int mf = 0; mf < 2; mf++) {
        int r0 = m0 + wm + mf * 16 + (lane >> 2);
#pragma unroll
        for (int nf = 0; nf < 8; nf++) {
            int col = wn + nf * 8 + (lane & 3) * 2;
            float b0 = bias[col], b1 = bias[col + 1];
            float x0 = acc[mf][nf][0] + b0, x1 = acc[mf][nf][1] + b1;
            float x2 = acc[mf][nf][2] + b0, x3 = acc[mf][nf][3] + b1;
            if (MODE == 1) {
                x0 = fmaxf(x0, 0.f); x1 = fmaxf(x1, 0.f);
                x2 = fmaxf(x2, 0.f); x3 = fmaxf(x3, 0.f);
            }
            if (r0 < NN)     *(float2*)(C + (size_t)r0 * D + col)       = make_float2(x0, x1);
            if (r0 + 8 < NN) *(float2*)(C + (size_t)(r0 + 8) * D + col) = make_float2(x2, x3);
        }
    }
}

// ---------------- BN statistics over g_h1 (fast separate pass) ---------------
__global__ void __launch_bounds__(256) k_stats() {   // grid 256 x 256
    int lane = threadIdx.x & 31, warp = threadIdx.x >> 5;
    float s0 = 0.f, s1 = 0.f, s2 = 0.f, s3 = 0.f;
    float q0 = 0.f, q1 = 0.f, q2 = 0.f, q3 = 0.f;
    for (int r = blockIdx.x * 8 + warp; r < NN; r += 2048) {
        float4 v = *(const float4*)(g_h1 + (size_t)r * D + lane * 4);
        s0 += v.x; q0 = fmaf(v.x, v.x, q0);
        s1 += v.y; q1 = fmaf(v.y, v.y, q1);
        s2 += v.z; q2 = fmaf(v.z, v.z, q2);
        s3 += v.w; q3 = fmaf(v.w, v.w, q3);
    }
    __shared__ float sm[8][132], sq[8][132];
    sm[warp][lane * 4]     = s0; sq[warp][lane * 4]     = q0;
    sm[warp][lane * 4 + 1] = s1; sq[warp][lane * 4 + 1] = q1;
    sm[warp][lane * 4 + 2] = s2; sq[warp][lane * 4 + 2] = q2;
    sm[warp][lane * 4 + 3] = s3; sq[warp][lane * 4 + 3] = q3;
    __syncthreads();
    int tid = threadIdx.x;
    if (tid < 128) {
        float t = 0.f;
#pragma unroll
        for (int j = 0; j < 8; j++) t += sm[j][tid];
        atomicAdd(&g_stats2[tid * 32], t);
    } else {
        int c = tid - 128;
        float t = 0.f;
#pragma unroll
        for (int j = 0; j < 8; j++) t += sq[j][c];
        atomicAdd(&g_stats2[(128 + c) * 32], t);
    }
}

// ---------------- BN finalize (also re-zeroes stats for the next layer) ------
__global__ void k_finalize(const float* __restrict__ gamma, const float* __restrict__ beta) {
    int c = threadIdx.x;
    float mean = g_stats2[c * 32] * (1.f / NN);
    float var  = g_stats2[(128 + c) * 32] * (1.f / NN) - mean * mean;  // biased var
    float sc   = gamma[c] * rsqrtf(var + BN_EPS);
    g_scale[c] = sc;
    g_shift[c] = fmaf(-mean, sc, beta[c]);
    g_stats2[c * 32] = 0.f;
    g_stats2[(128 + c) * 32] = 0.f;
}

// ---------------- per-graph pooling (sorted batch -> contiguous ranges) ------
__global__ void k_pool(const float* __restrict__ h, int layer) {
    int g = blockIdx.x, t = threadIdx.x;
    int i0 = g_gstart[g], i1 = g_gstart[g + 1];
    float s0 = 0.f, s1 = 0.f, s2 = 0.f, s3 = 0.f;
    int i = i0;
    for (; i + 4 <= i1; i += 4) {
        s0 += h[(size_t)(i    ) * D + t];
        s1 += h[(size_t)(i + 1) * D + t];
        s2 += h[(size_t)(i + 2) * D + t];
        s3 += h[(size_t)(i + 3) * D + t];
    }
    for (; i < i1; i++) s0 += h[(size_t)i * D + t];
    g_pooled[(size_t)g * (4 * D) + layer * D + t] = (s0 + s1) + (s2 + s3);
}

// ---------------- classifier --------------------------------------------------
__global__ void k_cls1(const float* __restrict__ cw1, const float* __restrict__ cb1) {
    int g = blockIdx.x, c = threadIdx.x;     // 128 threads
    const float* p = g_pooled + (size_t)g * (4 * D);
    float s = cb1[c];
#pragma unroll 8
    for (int k = 0; k < 4 * D; k++) s = fmaf(p[k], cw1[(size_t)k * D + c], s);
    g_c1[g * D + c] = fmaxf(s, 0.f);
}

__global__ void k_cls2(const float* __restrict__ cw2, const float* __restrict__ cb2) {
    int g = blockIdx.x, c = threadIdx.x;     // 64 threads
    const float* p = g_c1 + g * D;
    float s = cb2[c];
#pragma unroll 8
    for (int k = 0; k < D; k++) s = fmaf(p[k], cw2[k * (D / 2) + c], s);
    g_c2[g * (D / 2) + c] = fmaxf(s, 0.f);
}

__global__ void k_cls3(const float* __restrict__ cw3, const float* __restrict__ cb3,
                       float* __restrict__ out) {
    int id = blockIdx.x * blockDim.x + threadIdx.x;
    if (id >= NG * 2) return;
    int g = id >> 1, c = id & 1;
    const float* p = g_c2 + g * (D / 2);
    float s = cb3[c];
#pragma unroll
    for (int k = 0; k < D / 2; k++) s = fmaf(p[k], cw3[k * 2 + c], s);
    out[id] = s;
}

// ---------------- launcher ----------------------------------------------------
extern "C" void kernel_launch(void* const* d_in, const int* in_sizes, int n_in,
                              void* d_out, int out_size) {
    const float* x    = (const float*)d_in[0];
    const int*   ei   = (const int*)  d_in[1];
    const int*   bat  = (const int*)  d_in[2];
    const float* w1   = (const float*)d_in[3];
    const float* b1   = (const float*)d_in[4];
    const float* g1   = (const float*)d_in[5];
    const float* be1  = (const float*)d_in[6];
    const float* w2   = (const float*)d_in[7];
    const float* b2   = (const float*)d_in[8];
    const float* lw1  = (const float*)d_in[9];
    const float* lb1  = (const float*)d_in[10];
    const float* lg1  = (const float*)d_in[11];
    const float* lbe1 = (const float*)d_in[12];
    const float* lw2  = (const float*)d_in[13];
    const float* lb2  = (const float*)d_in[14];
    const float* cw1  = (const float*)d_in[15];
    const float* cb1  = (const float*)d_in[16];
    const float* cw2  = (const float*)d_in[17];
    const float* cb2  = (const float*)d_in[18];
    const float* cw3  = (const float*)d_in[19];
    const float* cb3  = (const float*)d_in[20];
    const int* src = ei;
    const int* dst = ei + NE;

    float *pAgg, *pH1, *pHA, *pHB, *pStats;
    int   *pCnt;
    cudaGetSymbolAddress((void**)&pAgg,   g_agg);
    cudaGetSymbolAddress((void**)&pH1,    g_h1);
    cudaGetSymbolAddress((void**)&pHA,    g_hA);
    cudaGetSymbolAddress((void**)&pHB,    g_hB);
    cudaGetSymbolAddress((void**)&pCnt,   g_cnt);
    cudaGetSymbolAddress((void**)&pStats, g_stats2);

    cudaMemsetAsync(pCnt,   0, (size_t)NN * sizeof(int));
    cudaMemsetAsync(pStats, 0, 256 * 32 * sizeof(float));

    // CSR by dst (rebuilt every call; deterministic inputs)
    k_hist<<<2048, 256>>>(dst);
    k_scan<<<1, 1024>>>(bat);
    k_scatter<<<2048, 256>>>(src, dst);

    const int GB = (NN + 127) / 128;   // 782 tiles
    const float* H = x;
    for (int l = 0; l < 4; l++) {
        const float *W1, *B1, *G, *BE, *W2, *B2;
        if (l == 0) { W1 = w1; B1 = b1; G = g1; BE = be1; W2 = w2; B2 = b2; }
        else {
            W1 = lw1 + (size_t)(l - 1) * D * D;  B1 = lb1 + (l - 1) * D;
            G  = lg1 + (l - 1) * D;              BE = lbe1 + (l - 1) * D;
            W2 = lw2 + (size_t)(l - 1) * D * D;  B2 = lb2 + (l - 1) * D;
        }
        k_agg<<<(NN + 3) / 4, 128>>>(H);
        k_gemm_tc<0><<<GB, 256>>>(pAgg, W1, B1, pH1);
        k_stats<<<256, 256>>>();
        k_finalize<<<1, 128>>>(G, BE);
        float* Hout = (l & 1) ? pHB : pHA;
        k_gemm_tc<1><<<GB, 256>>>(pH1, W2, B2, Hout);
        k_pool<<<NG, 128>>>(Hout, l);
        H = Hout;
    }

    k_cls1<<<NG, 128>>>(cw1, cb1);
    k_cls2<<<NG, 64>>>(cw2, cb2);
    k_cls3<<<8, 256>>>(cw3, cb3, (float*)d_out);
}

// round 11
// speedup vs baseline: 3.2153x; 1.0238x over previous
#include <cuda_runtime.h>
#include <cuda_bf16.h>

#define NN 100000
#define NE 3200000
#define NG 1024
#define D  128
#define BN_EPS 1e-5f
#define NPAD (NN + 128)   // padded rows so GEMM tile loads never run past the array

// ---------------- scratch (static device globals; no runtime alloc) ----------
__device__ __nv_bfloat16 g_aggh[(size_t)NPAD * D];  // split(agg) hi plane
__device__ __nv_bfloat16 g_aggl[(size_t)NPAD * D];  // split(agg) lo plane
__device__ float g_h1 [(size_t)NN * D];   // pre-BN hidden
__device__ float g_hA [(size_t)NN * D];   // layer output ping
__device__ float g_hB [(size_t)NN * D];   // layer output pong
__device__ int   g_rowptr[NN + 1];
__device__ int   g_cnt[NN];               // histogram, then fill cursor
__device__ int   g_csrc[NE];              // CSR: src node ids grouped by dst
// pre-split weights: index 2l = W1 of layer l, 2l+1 = W2 of layer l
__device__ __nv_bfloat16 g_wh[8 * D * D];
__device__ __nv_bfloat16 g_wl[8 * D * D];
// BN stats, one 128B line per scalar
__device__ float g_stats2[256 * 32];
__device__ float g_scale[D];
__device__ float g_shift[D];
__device__ float g_pooled[(size_t)NG * 4 * D];
__device__ int   g_gstart[NG + 1];
__device__ float g_c1[NG * D];
__device__ float g_c2[NG * (D / 2)];

// ---------------- mma/ldmatrix helpers ----------------------------------------
__device__ __forceinline__ unsigned smem_u32(const void* p) {
    return (unsigned)__cvta_generic_to_shared(p);
}
__device__ __forceinline__ void ldsm_x4(unsigned addr, unsigned& r0, unsigned& r1,
                                        unsigned& r2, unsigned& r3) {
    asm volatile("ldmatrix.sync.aligned.m8n8.x4.shared.b16 {%0,%1,%2,%3}, [%4];"
                 : "=r"(r0), "=r"(r1), "=r"(r2), "=r"(r3) : "r"(addr));
}
__device__ __forceinline__ void ldsm_x4t(unsigned addr, unsigned& r0, unsigned& r1,
                                         unsigned& r2, unsigned& r3) {
    asm volatile("ldmatrix.sync.aligned.m8n8.x4.trans.shared.b16 {%0,%1,%2,%3}, [%4];"
                 : "=r"(r0), "=r"(r1), "=r"(r2), "=r"(r3) : "r"(addr));
}
__device__ __forceinline__ void mma_bf16(float* d, const unsigned* a, const unsigned* b) {
    asm volatile(
        "mma.sync.aligned.m16n8k16.row.col.f32.bf16.bf16.f32 "
        "{%0,%1,%2,%3}, {%4,%5,%6,%7}, {%8,%9}, {%0,%1,%2,%3};"
        : "+f"(d[0]), "+f"(d[1]), "+f"(d[2]), "+f"(d[3])
        : "r"(a[0]), "r"(a[1]), "r"(a[2]), "r"(a[3]), "r"(b[0]), "r"(b[1]));
}
__device__ __forceinline__ void split_bf16(float v, __nv_bfloat16& h, __nv_bfloat16& l) {
    h = __float2bfloat16_rn(v);
    l = __float2bfloat16_rn(v - __bfloat162float(h));
}

// ---------------- weight pre-split: all 8 matrices, one kernel ----------------
__global__ void k_splitW(const float* __restrict__ w1, const float* __restrict__ w2,
                         const float* __restrict__ lw1, const float* __restrict__ lw2) {
    int f = blockIdx.x * blockDim.x + threadIdx.x;   // 32768 float4s
    int wi = f >> 12;            // 0..7
    int of = f & 4095;           // float4 within matrix
    const float* srcs[8] = { w1, w2, lw1, lw2, lw1 + D * D, lw2 + D * D,
                             lw1 + 2 * D * D, lw2 + 2 * D * D };
    float4 v = *(const float4*)(srcs[wi] + of * 4);
    __nv_bfloat16 h0, h1, h2, h3, l0, l1, l2, l3;
    split_bf16(v.x, h0, l0); split_bf16(v.y, h1, l1);
    split_bf16(v.z, h2, l2); split_bf16(v.w, h3, l3);
    __nv_bfloat162* ph = (__nv_bfloat162*)(g_wh + (size_t)wi * D * D + of * 4);
    __nv_bfloat162* pl = (__nv_bfloat162*)(g_wl + (size_t)wi * D * D + of * 4);
    ph[0] = __nv_bfloat162(h0, h1); ph[1] = __nv_bfloat162(h2, h3);
    pl[0] = __nv_bfloat162(l0, l1); pl[1] = __nv_bfloat162(l2, l3);
}

// ---------------- CSR build ---------------------------------------------------
__global__ void k_hist(const int* __restrict__ dst) {
    for (int e = blockIdx.x * blockDim.x + threadIdx.x; e < NE; e += gridDim.x * blockDim.x)
        atomicAdd(&g_cnt[dst[e]], 1);
}

__global__ void k_scan(const int* __restrict__ batch) {
    __shared__ int totals[1024];
    int t = threadIdx.x;
    const int CH = (NN + 1023) / 1024;   // 98
    int start = t * CH;
    int end   = start + CH; if (end > NN) end = NN;
    int s = 0;
    for (int i = start; i < end; i++) s += g_cnt[i];
    totals[t] = s;
    __syncthreads();
    if (t == 0) {
        int run = 0;
        for (int i = 0; i < 1024; i++) { int v = totals[i]; totals[i] = run; run += v; }
        g_rowptr[NN] = run;   // == NE
    }
    __syncthreads();
    int run = totals[t];
    for (int i = start; i < end; i++) {
        g_rowptr[i] = run; run += g_cnt[i];
        g_cnt[i] = 0;                       // reset cursor for scatter
    }
    {
        int lo = 0, hi = NN;
        while (lo < hi) { int mid = (lo + hi) >> 1; if (batch[mid] < t) lo = mid + 1; else hi = mid; }
        g_gstart[t] = lo;
        if (t == 0) g_gstart[NG] = NN;
    }
}

__global__ void k_scatter(const int* __restrict__ src, const int* __restrict__ dst) {
    for (int e = blockIdx.x * blockDim.x + threadIdx.x; e < NE; e += gridDim.x * blockDim.x) {
        int d = dst[e];
        int pos = g_rowptr[d] + atomicAdd(&g_cnt[d], 1);
        g_csrc[pos] = src[e];
    }
}

// ---------------- aggregation + bf16 split epilogue ---------------------------
// one warp per node, float4 per lane; writes hi/lo bf16 planes for GEMM1
__global__ void k_agg(const float* __restrict__ h) {
    int node = blockIdx.x * 4 + (threadIdx.x >> 5);
    int lane = threadIdx.x & 31;
    if (node >= NN) return;
    int e0 = g_rowptr[node], e1 = g_rowptr[node + 1];

    float4 acc = *(const float4*)(h + (size_t)node * D + lane * 4);
    int e = e0;
    for (; e + 4 <= e1; e += 4) {
        int s0 = g_csrc[e], s1 = g_csrc[e + 1], s2 = g_csrc[e + 2], s3 = g_csrc[e + 3];
        float4 v0 = *(const float4*)(h + (size_t)s0 * D + lane * 4);
        float4 v1 = *(const float4*)(h + (size_t)s1 * D + lane * 4);
        float4 v2 = *(const float4*)(h + (size_t)s2 * D + lane * 4);
        float4 v3 = *(const float4*)(h + (size_t)s3 * D + lane * 4);
        acc.x += (v0.x + v1.x) + (v2.x + v3.x);
        acc.y += (v0.y + v1.y) + (v2.y + v3.y);
        acc.z += (v0.z + v1.z) + (v2.z + v3.z);
        acc.w += (v0.w + v1.w) + (v2.w + v3.w);
    }
    for (; e < e1; e++) {
        float4 v = *(const float4*)(h + (size_t)g_csrc[e] * D + lane * 4);
        acc.x += v.x; acc.y += v.y; acc.z += v.z; acc.w += v.w;
    }
    __nv_bfloat16 h0, h1, h2, h3, l0, l1, l2, l3;
    split_bf16(acc.x, h0, l0); split_bf16(acc.y, h1, l1);
    split_bf16(acc.z, h2, l2); split_bf16(acc.w, h3, l3);
    __nv_bfloat162* ph = (__nv_bfloat162*)(g_aggh + (size_t)node * D + lane * 4);
    __nv_bfloat162* pl = (__nv_bfloat162*)(g_aggl + (size_t)node * D + lane * 4);
    ph[0] = __nv_bfloat162(h0, h1); ph[1] = __nv_bfloat162(h2, h3);
    pl[0] = __nv_bfloat162(l0, l1); pl[1] = __nv_bfloat162(l2, l3);
}

// ---------------- tensor-core GEMM ---------------------------------------------
// 128x128 tile, 8 warps (warp tile 32x64), bf16 2-way split, 3-term mma.
// MODE 0: A pre-split (g_aggh/g_aggl), no output relu.
// MODE 1: A raw fp32, A'=relu(A*scale+shift) split at stage, relu output.
// W always pre-split (Wh/Wl). Register prefetch of the next K chunk.
template <int MODE>
__global__ void __launch_bounds__(256) k_gemm_tc(const float* __restrict__ A,
                                                 const __nv_bfloat16* __restrict__ Wh,
                                                 const __nv_bfloat16* __restrict__ Wl,
                                                 const float* __restrict__ bias,
                                                 float* __restrict__ C) {
    constexpr int AP = 40;    // A smem pitch in bf16 (80B, conflict-free ldmatrix)
    constexpr int BP = 136;   // B smem pitch in bf16 (272B, conflict-free ldmatrix)
    __shared__ __nv_bfloat16 a_hi[128 * AP], a_lo[128 * AP];
    __shared__ __nv_bfloat16 b_hi[32 * BP],  b_lo[32 * BP];

    const int tid  = threadIdx.x;
    const int lane = tid & 31;
    const int warp = tid >> 5;
    const int wm = (warp >> 1) * 32;
    const int wn = (warp & 1) * 64;
    const int m0 = blockIdx.x * 128;

    float acc[2][8][4];
#pragma unroll
    for (int mf = 0; mf < 2; mf++)
#pragma unroll
        for (int nf = 0; nf < 8; nf++)
#pragma unroll
            for (int i = 0; i < 4; i++) acc[mf][nf][i] = 0.f;

    const int a_row = (lane & 7) + ((lane >> 3) & 1) * 8;
    const int a_kof = (lane >> 4) * 8;
    const int b_kof = (lane & 7) + ((lane >> 3) & 1) * 8;
    const int b_nof = (lane >> 4) * 8;

    // prefetch registers
    uint4  pah[2], pal[2];     // MODE 0: pre-split A copies (r=f>>2, kq=f&3)
    float4 par[4];             // MODE 1: raw A fp32     (r=f>>3, kq=f&7)
    uint4  pwh[2], pwl[2];     // W copies               (k=f>>4, q=f&15)

    auto loadA = [&](int k0) {
        if (MODE == 0) {
#pragma unroll
            for (int j = 0; j < 2; j++) {
                int f = j * 256 + tid;
                int r = f >> 2, kq = f & 3;
                size_t off = (size_t)(m0 + r) * D + k0 + kq * 8;
                pah[j] = *(const uint4*)(g_aggh + off);
                pal[j] = *(const uint4*)(g_aggl + off);
            }
        } else {
#pragma unroll
            for (int j = 0; j < 4; j++) {
                int f = j * 256 + tid;
                int r = f >> 3, kq = f & 7;
                int row = m0 + r;
                float4 v = make_float4(0.f, 0.f, 0.f, 0.f);
                if (row < NN) v = *(const float4*)(A + (size_t)row * D + k0 + kq * 4);
                float4 sc = *(const float4*)(g_scale + k0 + kq * 4);
                float4 sh = *(const float4*)(g_shift + k0 + kq * 4);
                v.x = fmaxf(fmaf(v.x, sc.x, sh.x), 0.f);
                v.y = fmaxf(fmaf(v.y, sc.y, sh.y), 0.f);
                v.z = fmaxf(fmaf(v.z, sc.z, sh.z), 0.f);
                v.w = fmaxf(fmaf(v.w, sc.w, sh.w), 0.f);
                par[j] = v;
            }
        }
    };
    auto loadW = [&](int k0) {
#pragma unroll
        for (int j = 0; j < 2; j++) {
            int f = j * 256 + tid;
            int k = f >> 4, q = f & 15;
            size_t off = (size_t)(k0 + k) * D + q * 8;
            pwh[j] = *(const uint4*)(Wh + off);
            pwl[j] = *(const uint4*)(Wl + off);
        }
    };
    auto storeA = [&]() {
        if (MODE == 0) {
#pragma unroll
            for (int j = 0; j < 2; j++) {
                int f = j * 256 + tid;
                int r = f >> 2, kq = f & 3;
                *(uint4*)&a_hi[r * AP + kq * 8] = pah[j];
                *(uint4*)&a_lo[r * AP + kq * 8] = pal[j];
            }
        } else {
#pragma unroll
            for (int j = 0; j < 4; j++) {
                int f = j * 256 + tid;
                int r = f >> 3, kq = f & 7;
                float4 v = par[j];
                __nv_bfloat16 h0, h1, h2, h3, l0, l1, l2, l3;
                split_bf16(v.x, h0, l0); split_bf16(v.y, h1, l1);
                split_bf16(v.z, h2, l2); split_bf16(v.w, h3, l3);
                __nv_bfloat162* ph = (__nv_bfloat162*)(a_hi + r * AP + kq * 4);
                __nv_bfloat162* pl = (__nv_bfloat162*)(a_lo + r * AP + kq * 4);
                ph[0] = __nv_bfloat162(h0, h1); ph[1] = __nv_bfloat162(h2, h3);
                pl[0] = __nv_bfloat162(l0, l1); pl[1] = __nv_bfloat162(l2, l3);
            }
        }
    };
    auto storeW = [&]() {
#pragma unroll
        for (int j = 0; j < 2; j++) {
            int f = j * 256 + tid;
            int k = f >> 4, q = f & 15;
            *(uint4*)&b_hi[k * BP + q * 8] = pwh[j];
            *(uint4*)&b_lo[k * BP + q * 8] = pwl[j];
        }
    };

    loadA(0); loadW(0);

#pragma unroll
    for (int t = 0; t < 4; t++) {
        storeA(); storeW();
        __syncthreads();
        if (t < 3) { loadA((t + 1) * 32); loadW((t + 1) * 32); }
#pragma unroll
        for (int ks = 0; ks < 32; ks += 16) {
            unsigned afh[2][4], afl[2][4];
#pragma unroll
            for (int mf = 0; mf < 2; mf++) {
                unsigned ah = smem_u32(a_hi + (wm + mf * 16 + a_row) * AP + ks + a_kof);
                unsigned al = smem_u32(a_lo + (wm + mf * 16 + a_row) * AP + ks + a_kof);
                ldsm_x4(ah, afh[mf][0], afh[mf][1], afh[mf][2], afh[mf][3]);
                ldsm_x4(al, afl[mf][0], afl[mf][1], afl[mf][2], afl[mf][3]);
            }
#pragma unroll
            for (int ng = 0; ng < 4; ng++) {
                unsigned bh[4], bl[4];
                int bc = wn + ng * 16 + b_nof;
                ldsm_x4t(smem_u32(b_hi + (ks + b_kof) * BP + bc), bh[0], bh[1], bh[2], bh[3]);
                ldsm_x4t(smem_u32(b_lo + (ks + b_kof) * BP + bc), bl[0], bl[1], bl[2], bl[3]);
#pragma unroll
                for (int mf = 0; mf < 2; mf++) {
                    mma_bf16(acc[mf][2 * ng],     afh[mf], bh);
                    mma_bf16(acc[mf][2 * ng],     afh[mf], bl);
                    mma_bf16(acc[mf][2 * ng],     afl[mf], bh);
                    mma_bf16(acc[mf][2 * ng + 1], afh[mf], bh + 2);
                    mma_bf16(acc[mf][2 * ng + 1], afh[mf], bl + 2);
                    mma_bf16(acc[mf][2 * ng + 1], afl[mf], bh + 2);
                }
            }
        }
        __syncthreads();
    }

#pragma unroll
    for (int mf = 0; mf < 2; mf++) {
        int r0 = m0 + wm + mf * 16 + (lane >> 2);
#pragma unroll
        for (int nf = 0; nf < 8; nf++) {
            int col = wn + nf * 8 + (lane & 3) * 2;
            float b0 = bias[col], b1 = bias[col + 1];
            float x0 = acc[mf][nf][0] + b0, x1 = acc[mf][nf][1] + b1;
            float x2 = acc[mf][nf][2] + b0, x3 = acc[mf][nf][3] + b1;
            if (MODE == 1) {
                x0 = fmaxf(x0, 0.f); x1 = fmaxf(x1, 0.f);
                x2 = fmaxf(x2, 0.f); x3 = fmaxf(x3, 0.f);
            }
            if (r0 < NN)     *(float2*)(C + (size_t)r0 * D + col)       = make_float2(x0, x1);
            if (r0 + 8 < NN) *(float2*)(C + (size_t)(r0 + 8) * D + col) = make_float2(x2, x3);
        }
    }
}

// ---------------- BN statistics over g_h1 ------------------------------------
__global__ void __launch_bounds__(256) k_stats() {   // grid 256 x 256
    int lane = threadIdx.x & 31, warp = threadIdx.x >> 5;
    float s0 = 0.f, s1 = 0.f, s2 = 0.f, s3 = 0.f;
    float q0 = 0.f, q1 = 0.f, q2 = 0.f, q3 = 0.f;
    for (int r = blockIdx.x * 8 + warp; r < NN; r += 2048) {
        float4 v = *(const float4*)(g_h1 + (size_t)r * D + lane * 4);
        s0 += v.x; q0 = fmaf(v.x, v.x, q0);
        s1 += v.y; q1 = fmaf(v.y, v.y, q1);
        s2 += v.z; q2 = fmaf(v.z, v.z, q2);
        s3 += v.w; q3 = fmaf(v.w, v.w, q3);
    }
    __shared__ float sm[8][132], sq[8][132];
    sm[warp][lane * 4]     = s0; sq[warp][lane * 4]     = q0;
    sm[warp][lane * 4 + 1] = s1; sq[warp][lane * 4 + 1] = q1;
    sm[warp][lane * 4 + 2] = s2; sq[warp][lane * 4 + 2] = q2;
    sm[warp][lane * 4 + 3] = s3; sq[warp][lane * 4 + 3] = q3;
    __syncthreads();
    int tid = threadIdx.x;
    if (tid < 128) {
        float t = 0.f;
#pragma unroll
        for (int j = 0; j < 8; j++) t += sm[j][tid];
        atomicAdd(&g_stats2[tid * 32], t);
    } else {
        int c = tid - 128;
        float t = 0.f;
#pragma unroll
        for (int j = 0; j < 8; j++) t += sq[j][c];
        atomicAdd(&g_stats2[(128 + c) * 32], t);
    }
}

// ---------------- BN finalize (re-zeroes stats for the next layer) -----------
__global__ void k_finalize(const float* __restrict__ gamma, const float* __restrict__ beta) {
    int c = threadIdx.x;
    float mean = g_stats2[c * 32] * (1.f / NN);
    float var  = g_stats2[(128 + c) * 32] * (1.f / NN) - mean * mean;
    float sc   = gamma[c] * rsqrtf(var + BN_EPS);
    g_scale[c] = sc;
    g_shift[c] = fmaf(-mean, sc, beta[c]);
    g_stats2[c * 32] = 0.f;
    g_stats2[(128 + c) * 32] = 0.f;
}

// ---------------- per-graph pooling -------------------------------------------
__global__ void k_pool(const float* __restrict__ h, int layer) {
    int g = blockIdx.x, t = threadIdx.x;
    int i0 = g_gstart[g], i1 = g_gstart[g + 1];
    float s0 = 0.f, s1 = 0.f, s2 = 0.f, s3 = 0.f;
    int i = i0;
    for (; i + 4 <= i1; i += 4) {
        s0 += h[(size_t)(i    ) * D + t];
        s1 += h[(size_t)(i + 1) * D + t];
        s2 += h[(size_t)(i + 2) * D + t];
        s3 += h[(size_t)(i + 3) * D + t];
    }
    for (; i < i1; i++) s0 += h[(size_t)i * D + t];
    g_pooled[(size_t)g * (4 * D) + layer * D + t] = (s0 + s1) + (s2 + s3);
}

// ---------------- classifier --------------------------------------------------
__global__ void k_cls1(const float* __restrict__ cw1, const float* __restrict__ cb1) {
    int g = blockIdx.x, c = threadIdx.x;
    const float* p = g_pooled + (size_t)g * (4 * D);
    float s = cb1[c];
#pragma unroll 8
    for (int k = 0; k < 4 * D; k++) s = fmaf(p[k], cw1[(size_t)k * D + c], s);
    g_c1[g * D + c] = fmaxf(s, 0.f);
}

__global__ void k_cls2(const float* __restrict__ cw2, const float* __restrict__ cb2) {
    int g = blockIdx.x, c = threadIdx.x;
    const float* p = g_c1 + g * D;
    float s = cb2[c];
#pragma unroll 8
    for (int k = 0; k < D; k++) s = fmaf(p[k], cw2[k * (D / 2) + c], s);
    g_c2[g * (D / 2) + c] = fmaxf(s, 0.f);
}

__global__ void k_cls3(const float* __restrict__ cw3, const float* __restrict__ cb3,
                       float* __restrict__ out) {
    int id = blockIdx.x * blockDim.x + threadIdx.x;
    if (id >= NG * 2) return;
    int g = id >> 1, c = id & 1;
    const float* p = g_c2 + g * (D / 2);
    float s = cb3[c];
#pragma unroll
    for (int k = 0; k < D / 2; k++) s = fmaf(p[k], cw3[k * 2 + c], s);
    out[id] = s;
}

// ---------------- launcher ----------------------------------------------------
extern "C" void kernel_launch(void* const* d_in, const int* in_sizes, int n_in,
                              void* d_out, int out_size) {
    const float* x    = (const float*)d_in[0];
    const int*   ei   = (const int*)  d_in[1];
    const int*   bat  = (const int*)  d_in[2];
    const float* w1   = (const float*)d_in[3];
    const float* b1   = (const float*)d_in[4];
    const float* g1   = (const float*)d_in[5];
    const float* be1  = (const float*)d_in[6];
    const float* w2   = (const float*)d_in[7];
    const float* b2   = (const float*)d_in[8];
    const float* lw1  = (const float*)d_in[9];
    const float* lb1  = (const float*)d_in[10];
    const float* lg1  = (const float*)d_in[11];
    const float* lbe1 = (const float*)d_in[12];
    const float* lw2  = (const float*)d_in[13];
    const float* lb2  = (const float*)d_in[14];
    const float* cw1  = (const float*)d_in[15];
    const float* cb1  = (const float*)d_in[16];
    const float* cw2  = (const float*)d_in[17];
    const float* cb2  = (const float*)d_in[18];
    const float* cw3  = (const float*)d_in[19];
    const float* cb3  = (const float*)d_in[20];
    const int* src = ei;
    const int* dst = ei + NE;

    float *pH1, *pHA, *pHB, *pStats;
    int   *pCnt;
    __nv_bfloat16 *pWh, *pWl;
    cudaGetSymbolAddress((void**)&pH1,    g_h1);
    cudaGetSymbolAddress((void**)&pHA,    g_hA);
    cudaGetSymbolAddress((void**)&pHB,    g_hB);
    cudaGetSymbolAddress((void**)&pCnt,   g_cnt);
    cudaGetSymbolAddress((void**)&pStats, g_stats2);
    cudaGetSymbolAddress((void**)&pWh,    g_wh);
    cudaGetSymbolAddress((void**)&pWl,    g_wl);

    cudaMemsetAsync(pCnt,   0, (size_t)NN * sizeof(int));
    cudaMemsetAsync(pStats, 0, 256 * 32 * sizeof(float));

    k_splitW<<<128, 256>>>(w1, w2, lw1, lw2);    // all 8 weight matrices
    k_hist<<<2048, 256>>>(dst);
    k_scan<<<1, 1024>>>(bat);
    k_scatter<<<2048, 256>>>(src, dst);

    const int GB = (NN + 127) / 128;   // 782 tiles
    const float* H = x;
    for (int l = 0; l < 4; l++) {
        const float *B1, *G, *BE, *B2;
        if (l == 0) { B1 = b1; G = g1; BE = be1; B2 = b2; }
        else {
            B1 = lb1 + (l - 1) * D;  G  = lg1 + (l - 1) * D;
            BE = lbe1 + (l - 1) * D; B2 = lb2 + (l - 1) * D;
        }
        const __nv_bfloat16* W1h = pWh + (size_t)(2 * l)     * D * D;
        const __nv_bfloat16* W1l = pWl + (size_t)(2 * l)     * D * D;
        const __nv_bfloat16* W2h = pWh + (size_t)(2 * l + 1) * D * D;
        const __nv_bfloat16* W2l = pWl + (size_t)(2 * l + 1) * D * D;

        k_agg<<<(NN + 3) / 4, 128>>>(H);
        k_gemm_tc<0><<<GB, 256>>>(nullptr, W1h, W1l, B1, pH1);
        k_stats<<<256, 256>>>();
        k_finalize<<<1, 128>>>(G, BE);
        float* Hout = (l & 1) ? pHB : pHA;
        k_gemm_tc<1><<<GB, 256>>>(pH1, W2h, W2l, B2, Hout);
        k_pool<<<NG, 128>>>(Hout, l);
        H = Hout;
    }

    k_cls1<<<NG, 128>>>(cw1, cb1);
    k_cls2<<<NG, 64>>>(cw2, cb2);
    k_cls3<<<8, 256>>>(cw3, cb3, (float*)d_out);
}

// round 13
// speedup vs baseline: 3.3079x; 1.0288x over previous
#include <cuda_runtime.h>
#include <cuda_bf16.h>

#define NN 100000
#define NE 3200000
#define NG 1024
#define D  128
#define BN_EPS 1e-5f
#define NPAD (NN + 128)

// ---------------- scratch (static device globals; no runtime alloc) ----------
__device__ __nv_bfloat16 g_aggh[(size_t)NPAD * D];  // split(agg) hi plane
__device__ __nv_bfloat16 g_aggl[(size_t)NPAD * D];  // split(agg) lo plane
__device__ float g_h1 [(size_t)NN * D];
__device__ float g_hA [(size_t)NN * D];
__device__ float g_hB [(size_t)NN * D];
__device__ int   g_rowptr[NN + 1];
__device__ int   g_cnt[NN];
__device__ int   g_csrc[NE];
__device__ __nv_bfloat16 g_wh[8 * D * D];   // pre-split weights (2l=W1, 2l+1=W2)
__device__ __nv_bfloat16 g_wl[8 * D * D];
__device__ float g_stats2[256 * 32];        // one 128B line per scalar
__device__ float g_scale[D];
__device__ float g_shift[D];
__device__ float g_pooled[(size_t)NG * 4 * D];
__device__ int   g_gstart[NG + 1];
__device__ float g_c1[NG * D];
__device__ float g_c2[NG * (D / 2)];

// ---------------- mma/ldmatrix helpers ----------------------------------------
__device__ __forceinline__ unsigned smem_u32(const void* p) {
    return (unsigned)__cvta_generic_to_shared(p);
}
__device__ __forceinline__ void ldsm_x4(unsigned addr, unsigned& r0, unsigned& r1,
                                        unsigned& r2, unsigned& r3) {
    asm volatile("ldmatrix.sync.aligned.m8n8.x4.shared.b16 {%0,%1,%2,%3}, [%4];"
                 : "=r"(r0), "=r"(r1), "=r"(r2), "=r"(r3) : "r"(addr));
}
__device__ __forceinline__ void ldsm_x4t(unsigned addr, unsigned& r0, unsigned& r1,
                                         unsigned& r2, unsigned& r3) {
    asm volatile("ldmatrix.sync.aligned.m8n8.x4.trans.shared.b16 {%0,%1,%2,%3}, [%4];"
                 : "=r"(r0), "=r"(r1), "=r"(r2), "=r"(r3) : "r"(addr));
}
__device__ __forceinline__ void mma_bf16(float* d, const unsigned* a, const unsigned* b) {
    asm volatile(
        "mma.sync.aligned.m16n8k16.row.col.f32.bf16.bf16.f32 "
        "{%0,%1,%2,%3}, {%4,%5,%6,%7}, {%8,%9}, {%0,%1,%2,%3};"
        : "+f"(d[0]), "+f"(d[1]), "+f"(d[2]), "+f"(d[3])
        : "r"(a[0]), "r"(a[1]), "r"(a[2]), "r"(a[3]), "r"(b[0]), "r"(b[1]));
}
__device__ __forceinline__ void split_bf16(float v, __nv_bfloat16& h, __nv_bfloat16& l) {
    h = __float2bfloat16_rn(v);
    l = __float2bfloat16_rn(v - __bfloat162float(h));
}

// ---------------- weight pre-split ---------------------------------------------
__global__ void k_splitW(const float* __restrict__ w1, const float* __restrict__ w2,
                         const float* __restrict__ lw1, const float* __restrict__ lw2) {
    int f = blockIdx.x * blockDim.x + threadIdx.x;   // 32768 float4s
    int wi = f >> 12;
    int of = f & 4095;
    const float* srcs[8] = { w1, w2, lw1, lw2, lw1 + D * D, lw2 + D * D,
                             lw1 + 2 * D * D, lw2 + 2 * D * D };
    float4 v = *(const float4*)(srcs[wi] + of * 4);
    __nv_bfloat16 h0, h1, h2, h3, l0, l1, l2, l3;
    split_bf16(v.x, h0, l0); split_bf16(v.y, h1, l1);
    split_bf16(v.z, h2, l2); split_bf16(v.w, h3, l3);
    __nv_bfloat162* ph = (__nv_bfloat162*)(g_wh + (size_t)wi * D * D + of * 4);
    __nv_bfloat162* pl = (__nv_bfloat162*)(g_wl + (size_t)wi * D * D + of * 4);
    ph[0] = __nv_bfloat162(h0, h1); ph[1] = __nv_bfloat162(h2, h3);
    pl[0] = __nv_bfloat162(l0, l1); pl[1] = __nv_bfloat162(l2, l3);
}

// ---------------- CSR build ---------------------------------------------------
__global__ void k_hist(const int* __restrict__ dst) {
    for (int e = blockIdx.x * blockDim.x + threadIdx.x; e < NE; e += gridDim.x * blockDim.x)
        atomicAdd(&g_cnt[dst[e]], 1);
}

__global__ void k_scan(const int* __restrict__ batch) {
    __shared__ int totals[1024];
    int t = threadIdx.x;
    const int CH = (NN + 1023) / 1024;
    int start = t * CH;
    int end   = start + CH; if (end > NN) end = NN;
    int s = 0;
    for (int i = start; i < end; i++) s += g_cnt[i];
    totals[t] = s;
    __syncthreads();
    if (t == 0) {
        int run = 0;
        for (int i = 0; i < 1024; i++) { int v = totals[i]; totals[i] = run; run += v; }
        g_rowptr[NN] = run;
    }
    __syncthreads();
    int run = totals[t];
    for (int i = start; i < end; i++) {
        g_rowptr[i] = run; run += g_cnt[i];
        g_cnt[i] = 0;
    }
    {
        int lo = 0, hi = NN;
        while (lo < hi) { int mid = (lo + hi) >> 1; if (batch[mid] < t) lo = mid + 1; else hi = mid; }
        g_gstart[t] = lo;
        if (t == 0) g_gstart[NG] = NN;
    }
}

__global__ void k_scatter(const int* __restrict__ src, const int* __restrict__ dst) {
    for (int e = blockIdx.x * blockDim.x + threadIdx.x; e < NE; e += gridDim.x * blockDim.x) {
        int d = dst[e];
        int pos = g_rowptr[d] + atomicAdd(&g_cnt[d], 1);
        g_csrc[pos] = src[e];
    }
}

// ---------------- aggregation + bf16 split epilogue ---------------------------
__global__ void k_agg(const float* __restrict__ h) {
    int node = blockIdx.x * 4 + (threadIdx.x >> 5);
    int lane = threadIdx.x & 31;
    if (node >= NN) return;
    int e0 = g_rowptr[node], e1 = g_rowptr[node + 1];

    float4 acc = *(const float4*)(h + (size_t)node * D + lane * 4);
    int e = e0;
    for (; e + 4 <= e1; e += 4) {
        int s0 = g_csrc[e], s1 = g_csrc[e + 1], s2 = g_csrc[e + 2], s3 = g_csrc[e + 3];
        float4 v0 = *(const float4*)(h + (size_t)s0 * D + lane * 4);
        float4 v1 = *(const float4*)(h + (size_t)s1 * D + lane * 4);
        float4 v2 = *(const float4*)(h + (size_t)s2 * D + lane * 4);
        float4 v3 = *(const float4*)(h + (size_t)s3 * D + lane * 4);
        acc.x += (v0.x + v1.x) + (v2.x + v3.x);
        acc.y += (v0.y + v1.y) + (v2.y + v3.y);
        acc.z += (v0.z + v1.z) + (v2.z + v3.z);
        acc.w += (v0.w + v1.w) + (v2.w + v3.w);
    }
    for (; e < e1; e++) {
        float4 v = *(const float4*)(h + (size_t)g_csrc[e] * D + lane * 4);
        acc.x += v.x; acc.y += v.y; acc.z += v.z; acc.w += v.w;
    }
    __nv_bfloat16 h0, h1, h2, h3, l0, l1, l2, l3;
    split_bf16(acc.x, h0, l0); split_bf16(acc.y, h1, l1);
    split_bf16(acc.z, h2, l2); split_bf16(acc.w, h3, l3);
    __nv_bfloat162* ph = (__nv_bfloat162*)(g_aggh + (size_t)node * D + lane * 4);
    __nv_bfloat162* pl = (__nv_bfloat162*)(g_aggl + (size_t)node * D + lane * 4);
    ph[0] = __nv_bfloat162(h0, h1); ph[1] = __nv_bfloat162(h2, h3);
    pl[0] = __nv_bfloat162(l0, l1); pl[1] = __nv_bfloat162(l2, l3);
}

// ---------------- full-K-resident tensor-core GEMM ----------------------------
// 128x128 tile, 512 threads (16 warps, warp tile 32x32), full K=128 in smem,
// single stage + single sync, 3-term bf16-split mma, dynamic smem ~137KB.
// MODE 0: A = pre-split g_aggh/g_aggl; fused BN stats; no output relu.
// MODE 1: A raw fp32 with BN scale/shift + relu at stage; relu output.
#define AP 136   // smem pitch in bf16 (272B rows)

template <int MODE>
__global__ void __launch_bounds__(512) k_gemm_tc(const float* __restrict__ A,
                                                 const __nv_bfloat16* __restrict__ Wh,
                                                 const __nv_bfloat16* __restrict__ Wl,
                                                 const float* __restrict__ bias,
                                                 float* __restrict__ C) {
    extern __shared__ char dsm[];
    __nv_bfloat16* a_hi = (__nv_bfloat16*)dsm;
    __nv_bfloat16* a_lo = a_hi + 128 * AP;
    __nv_bfloat16* b_hi = a_lo + 128 * AP;
    __nv_bfloat16* b_lo = b_hi + 128 * AP;
    float* s_sum = (float*)(b_lo + 128 * AP);
    float* s_sq  = s_sum + 128;

    const int tid  = threadIdx.x;
    const int lane = tid & 31;
    const int warp = tid >> 5;                 // 0..15
    const int wm = (warp >> 2) * 32;           // 0/32/64/96
    const int wn = (warp & 3) * 32;            // 0/32/64/96
    const int m0 = blockIdx.x * 128;

    // ---- stage W (both planes): 2048 uint4 per plane, 512 threads -> 4 iters
#pragma unroll
    for (int j = 0; j < 4; j++) {
        int f = j * 512 + tid;
        int k = f >> 4, q = f & 15;
        size_t off = (size_t)k * D + q * 8;
        *(uint4*)&b_hi[k * AP + q * 8] = *(const uint4*)(Wh + off);
        *(uint4*)&b_lo[k * AP + q * 8] = *(const uint4*)(Wl + off);
    }
    // ---- stage A
    if (MODE == 0) {
#pragma unroll
        for (int j = 0; j < 4; j++) {
            int f = j * 512 + tid;
            int r = f >> 4, q = f & 15;
            size_t off = (size_t)(m0 + r) * D + q * 8;
            *(uint4*)&a_hi[r * AP + q * 8] = *(const uint4*)(g_aggh + off);
            *(uint4*)&a_lo[r * AP + q * 8] = *(const uint4*)(g_aggl + off);
        }
        if (tid < 128) { s_sum[tid] = 0.f; s_sq[tid] = 0.f; }
    } else {
#pragma unroll
        for (int j = 0; j < 8; j++) {
            int f = j * 512 + tid;
            int r = f >> 5, q = f & 31;          // q = float4 index
            int row = m0 + r;
            float4 v = make_float4(0.f, 0.f, 0.f, 0.f);
            if (row < NN) v = *(const float4*)(A + (size_t)row * D + q * 4);
            float4 sc = *(const float4*)(g_scale + q * 4);
            float4 sh = *(const float4*)(g_shift + q * 4);
            v.x = fmaxf(fmaf(v.x, sc.x, sh.x), 0.f);
            v.y = fmaxf(fmaf(v.y, sc.y, sh.y), 0.f);
            v.z = fmaxf(fmaf(v.z, sc.z, sh.z), 0.f);
            v.w = fmaxf(fmaf(v.w, sc.w, sh.w), 0.f);
            __nv_bfloat16 h0, h1, h2, h3, l0, l1, l2, l3;
            split_bf16(v.x, h0, l0); split_bf16(v.y, h1, l1);
            split_bf16(v.z, h2, l2); split_bf16(v.w, h3, l3);
            __nv_bfloat162* ph = (__nv_bfloat162*)(a_hi + r * AP + q * 4);
            __nv_bfloat162* pl = (__nv_bfloat162*)(a_lo + r * AP + q * 4);
            ph[0] = __nv_bfloat162(h0, h1); ph[1] = __nv_bfloat162(h2, h3);
            pl[0] = __nv_bfloat162(l0, l1); pl[1] = __nv_bfloat162(l2, l3);
        }
    }
    __syncthreads();

    float acc[2][4][4];
#pragma unroll
    for (int mf = 0; mf < 2; mf++)
#pragma unroll
        for (int nf = 0; nf < 4; nf++)
#pragma unroll
            for (int i = 0; i < 4; i++) acc[mf][nf][i] = 0.f;

    const int a_row = (lane & 7) + ((lane >> 3) & 1) * 8;
    const int a_kof = (lane >> 4) * 8;
    const int b_kof = (lane & 7) + ((lane >> 3) & 1) * 8;
    const int b_nof = (lane >> 4) * 8;

#pragma unroll
    for (int k = 0; k < D; k += 16) {
        unsigned afh[2][4], afl[2][4];
#pragma unroll
        for (int mf = 0; mf < 2; mf++) {
            unsigned ah = smem_u32(a_hi + (wm + mf * 16 + a_row) * AP + k + a_kof);
            unsigned al = smem_u32(a_lo + (wm + mf * 16 + a_row) * AP + k + a_kof);
            ldsm_x4(ah, afh[mf][0], afh[mf][1], afh[mf][2], afh[mf][3]);
            ldsm_x4(al, afl[mf][0], afl[mf][1], afl[mf][2], afl[mf][3]);
        }
#pragma unroll
        for (int ng = 0; ng < 2; ng++) {
            unsigned bh[4], bl[4];
            int bc = wn + ng * 16 + b_nof;
            ldsm_x4t(smem_u32(b_hi + (k + b_kof) * AP + bc), bh[0], bh[1], bh[2], bh[3]);
            ldsm_x4t(smem_u32(b_lo + (k + b_kof) * AP + bc), bl[0], bl[1], bl[2], bl[3]);
#pragma unroll
            for (int mf = 0; mf < 2; mf++) {
                mma_bf16(acc[mf][2 * ng],     afh[mf], bh);
                mma_bf16(acc[mf][2 * ng],     afh[mf], bl);
                mma_bf16(acc[mf][2 * ng],     afl[mf], bh);
                mma_bf16(acc[mf][2 * ng + 1], afh[mf], bh + 2);
                mma_bf16(acc[mf][2 * ng + 1], afh[mf], bl + 2);
                mma_bf16(acc[mf][2 * ng + 1], afl[mf], bh + 2);
            }
        }
    }

    // ---- epilogue ------------------------------------------------------------
    float st_s[8], st_q[8];
    if (MODE == 0) {
#pragma unroll
        for (int i = 0; i < 8; i++) { st_s[i] = 0.f; st_q[i] = 0.f; }
    }
#pragma unroll
    for (int mf = 0; mf < 2; mf++) {
        int r0 = m0 + wm + mf * 16 + (lane >> 2);
#pragma unroll
        for (int nf = 0; nf < 4; nf++) {
            int col = wn + nf * 8 + (lane & 3) * 2;
            float b0 = bias[col], b1 = bias[col + 1];
            float x0 = acc[mf][nf][0] + b0, x1 = acc[mf][nf][1] + b1;
            float x2 = acc[mf][nf][2] + b0, x3 = acc[mf][nf][3] + b1;
            if (MODE == 1) {
                x0 = fmaxf(x0, 0.f); x1 = fmaxf(x1, 0.f);
                x2 = fmaxf(x2, 0.f); x3 = fmaxf(x3, 0.f);
            }
            if (r0 < NN) {
                *(float2*)(C + (size_t)r0 * D + col) = make_float2(x0, x1);
                if (MODE == 0) {
                    st_s[nf * 2]     += x0; st_q[nf * 2]     = fmaf(x0, x0, st_q[nf * 2]);
                    st_s[nf * 2 + 1] += x1; st_q[nf * 2 + 1] = fmaf(x1, x1, st_q[nf * 2 + 1]);
                }
            }
            if (r0 + 8 < NN) {
                *(float2*)(C + (size_t)(r0 + 8) * D + col) = make_float2(x2, x3);
                if (MODE == 0) {
                    st_s[nf * 2]     += x2; st_q[nf * 2]     = fmaf(x2, x2, st_q[nf * 2]);
                    st_s[nf * 2 + 1] += x3; st_q[nf * 2 + 1] = fmaf(x3, x3, st_q[nf * 2 + 1]);
                }
            }
        }
    }

    if (MODE == 0) {
        // lanes sharing (lane&3) hold the same 8 columns -> butterfly over bits 2..4
#pragma unroll
        for (int off = 4; off < 32; off <<= 1) {
#pragma unroll
            for (int i = 0; i < 8; i++) {
                st_s[i] += __shfl_xor_sync(0xffffffffu, st_s[i], off);
                st_q[i] += __shfl_xor_sync(0xffffffffu, st_q[i], off);
            }
        }
        if (lane < 4) {
#pragma unroll
            for (int nf = 0; nf < 4; nf++) {
                int col = wn + nf * 8 + lane * 2;
                atomicAdd(&s_sum[col],     st_s[nf * 2]);
                atomicAdd(&s_sum[col + 1], st_s[nf * 2 + 1]);
                atomicAdd(&s_sq[col],      st_q[nf * 2]);
                atomicAdd(&s_sq[col + 1],  st_q[nf * 2 + 1]);
            }
        }
        __syncthreads();
        if (tid < 128)      atomicAdd(&g_stats2[tid * 32], s_sum[tid]);
        else if (tid < 256) atomicAdd(&g_stats2[(tid - 128 + 128) * 32], s_sq[tid - 128]);
    }
}

// ---------------- BN finalize (re-zeroes stats for the next layer) -----------
__global__ void k_finalize(const float* __restrict__ gamma, const float* __restrict__ beta) {
    int c = threadIdx.x;
    float mean = g_stats2[c * 32] * (1.f / NN);
    float var  = g_stats2[(128 + c) * 32] * (1.f / NN) - mean * mean;
    float sc   = gamma[c] * rsqrtf(var + BN_EPS);
    g_scale[c] = sc;
    g_shift[c] = fmaf(-mean, sc, beta[c]);
    g_stats2[c * 32] = 0.f;
    g_stats2[(128 + c) * 32] = 0.f;
}

// ---------------- per-graph pooling -------------------------------------------
__global__ void k_pool(const float* __restrict__ h, int layer) {
    int g = blockIdx.x, t = threadIdx.x;
    int i0 = g_gstart[g], i1 = g_gstart[g + 1];
    float s0 = 0.f, s1 = 0.f, s2 = 0.f, s3 = 0.f;
    int i = i0;
    for (; i + 4 <= i1; i += 4) {
        s0 += h[(size_t)(i    ) * D + t];
        s1 += h[(size_t)(i + 1) * D + t];
        s2 += h[(size_t)(i + 2) * D + t];
        s3 += h[(size_t)(i + 3) * D + t];
    }
    for (; i < i1; i++) s0 += h[(size_t)i * D + t];
    g_pooled[(size_t)g * (4 * D) + layer * D + t] = (s0 + s1) + (s2 + s3);
}

// ---------------- classifier --------------------------------------------------
__global__ void k_cls1(const float* __restrict__ cw1, const float* __restrict__ cb1) {
    int g = blockIdx.x, c = threadIdx.x;
    const float* p = g_pooled + (size_t)g * (4 * D);
    float s = cb1[c];
#pragma unroll 8
    for (int k = 0; k < 4 * D; k++) s = fmaf(p[k], cw1[(size_t)k * D + c], s);
    g_c1[g * D + c] = fmaxf(s, 0.f);
}

__global__ void k_cls2(const float* __restrict__ cw2, const float* __restrict__ cb2) {
    int g = blockIdx.x, c = threadIdx.x;
    const float* p = g_c1 + g * D;
    float s = cb2[c];
#pragma unroll 8
    for (int k = 0; k < D; k++) s = fmaf(p[k], cw2[k * (D / 2) + c], s);
    g_c2[g * (D / 2) + c] = fmaxf(s, 0.f);
}

__global__ void k_cls3(const float* __restrict__ cw3, const float* __restrict__ cb3,
                       float* __restrict__ out) {
    int id = blockIdx.x * blockDim.x + threadIdx.x;
    if (id >= NG * 2) return;
    int g = id >> 1, c = id & 1;
    const float* p = g_c2 + g * (D / 2);
    float s = cb3[c];
#pragma unroll
    for (int k = 0; k < D / 2; k++) s = fmaf(p[k], cw3[k * 2 + c], s);
    out[id] = s;
}

// ---------------- launcher ----------------------------------------------------
extern "C" void kernel_launch(void* const* d_in, const int* in_sizes, int n_in,
                              void* d_out, int out_size) {
    const float* x    = (const float*)d_in[0];
    const int*   ei   = (const int*)  d_in[1];
    const int*   bat  = (const int*)  d_in[2];
    const float* w1   = (const float*)d_in[3];
    const float* b1   = (const float*)d_in[4];
    const float* g1   = (const float*)d_in[5];
    const float* be1  = (const float*)d_in[6];
    const float* w2   = (const float*)d_in[7];
    const float* b2   = (const float*)d_in[8];
    const float* lw1  = (const float*)d_in[9];
    const float* lb1  = (const float*)d_in[10];
    const float* lg1  = (const float*)d_in[11];
    const float* lbe1 = (const float*)d_in[12];
    const float* lw2  = (const float*)d_in[13];
    const float* lb2  = (const float*)d_in[14];
    const float* cw1  = (const float*)d_in[15];
    const float* cb1  = (const float*)d_in[16];
    const float* cw2  = (const float*)d_in[17];
    const float* cb2  = (const float*)d_in[18];
    const float* cw3  = (const float*)d_in[19];
    const float* cb3  = (const float*)d_in[20];
    const int* src = ei;
    const int* dst = ei + NE;

    float *pH1, *pHA, *pHB, *pStats;
    int   *pCnt;
    __nv_bfloat16 *pWh, *pWl, *pAh, *pAl;
    cudaGetSymbolAddress((void**)&pH1,    g_h1);
    cudaGetSymbolAddress((void**)&pHA,    g_hA);
    cudaGetSymbolAddress((void**)&pHB,    g_hB);
    cudaGetSymbolAddress((void**)&pCnt,   g_cnt);
    cudaGetSymbolAddress((void**)&pStats, g_stats2);
    cudaGetSymbolAddress((void**)&pWh,    g_wh);
    cudaGetSymbolAddress((void**)&pWl,    g_wl);
    cudaGetSymbolAddress((void**)&pAh,    g_aggh);
    cudaGetSymbolAddress((void**)&pAl,    g_aggl);

    // dynamic smem opt-in: 4 planes of 128*AP bf16 + 2*128 floats = 140288 B
    const int SMEM_SZ = 4 * 128 * AP * 2 + 2 * 128 * 4;
    cudaFuncSetAttribute(k_gemm_tc<0>, cudaFuncAttributeMaxDynamicSharedMemorySize, SMEM_SZ);
    cudaFuncSetAttribute(k_gemm_tc<1>, cudaFuncAttributeMaxDynamicSharedMemorySize, SMEM_SZ);

    cudaMemsetAsync(pCnt,   0, (size_t)NN * sizeof(int));
    cudaMemsetAsync(pStats, 0, 256 * 32 * sizeof(float));
    // zero pad rows of split planes (keeps staged garbage out of smem)
    cudaMemsetAsync(pAh + (size_t)NN * D, 0, (size_t)(NPAD - NN) * D * sizeof(__nv_bfloat16));
    cudaMemsetAsync(pAl + (size_t)NN * D, 0, (size_t)(NPAD - NN) * D * sizeof(__nv_bfloat16));

    k_splitW<<<128, 256>>>(w1, w2, lw1, lw2);
    k_hist<<<2048, 256>>>(dst);
    k_scan<<<1, 1024>>>(bat);
    k_scatter<<<2048, 256>>>(src, dst);

    const int GB = (NN + 127) / 128;   // 782 tiles
    const float* H = x;
    for (int l = 0; l < 4; l++) {
        const float *B1, *G, *BE, *B2;
        if (l == 0) { B1 = b1; G = g1; BE = be1; B2 = b2; }
        else {
            B1 = lb1 + (l - 1) * D;  G  = lg1 + (l - 1) * D;
            BE = lbe1 + (l - 1) * D; B2 = lb2 + (l - 1) * D;
        }
        const __nv_bfloat16* W1h = pWh + (size_t)(2 * l)     * D * D;
        const __nv_bfloat16* W1l = pWl + (size_t)(2 * l)     * D * D;
        const __nv_bfloat16* W2h = pWh + (size_t)(2 * l + 1) * D * D;
        const __nv_bfloat16* W2l = pWl + (size_t)(2 * l + 1) * D * D;

        k_agg<<<(NN + 3) / 4, 128>>>(H);
        k_gemm_tc<0><<<GB, 512, SMEM_SZ>>>(nullptr, W1h, W1l, B1, pH1);
        k_finalize<<<1, 128>>>(G, BE);
        float* Hout = (l & 1) ? pHB : pHA;
        k_gemm_tc<1><<<GB, 512, SMEM_SZ>>>(pH1, W2h, W2l, B2, Hout);
        k_pool<<<NG, 128>>>(Hout, l);
        H = Hout;
    }

    k_cls1<<<NG, 128>>>(cw1, cb1);
    k_cls2<<<NG, 64>>>(cw2, cb2);
    k_cls3<<<8, 256>>>(cw3, cb3, (float*)d_out);
}